// round 11
// baseline (speedup 1.0000x reference)
#include <cuda_runtime.h>

#define BATCH     65536
#define TM        64
#define NTH       512
#define RES_SCALE 0.70710678118654752440f
#define GAMMA_C   1.5f

// folded BN affine tables: y = acc*A + C
#define OFF_IN    0
#define OFF_SH0   320
#define OFF_SH1   576
#define OFF_INIT  832
#define OFF_STEP  1344
#define OFF_ATT   3904
#define AC_TOTAL  4304

__device__ float g_A[AC_TOTAL];
__device__ float g_C[AC_TOTAL];

// activation layout: element (col, r) -> col*64 + (r ^ (col & 0x1C))
#define SWZ(col, r) ((col) * 64 + ((r) ^ ((col) & 0x1C)))

#define FMA2(acc, a, b) \
    asm("fma.rn.f32x2 %0, %1, %2, %0;" : "+l"(acc) : "l"(a), "l"(b))
#define PACKDUP(dst, v) \
    asm("mov.b64 %0, {%1, %1};" : "=l"(dst) : "r"(__float_as_uint(v)))
#define UNPACK2(lo, hi, v) \
    asm("mov.b64 {%0, %1}, %2;" : "=f"(lo), "=f"(hi) : "l"(v))

__device__ __forceinline__ void cp16(unsigned dst, const float* src) {
    asm volatile("cp.async.ca.shared.global [%0], [%1], 16;\n"
                 :: "r"(dst), "l"(src));
}
#define CP_COMMIT() asm volatile("cp.async.commit_group;\n" ::: "memory")
#define CP_WAIT0()  asm volatile("cp.async.wait_group 0;\n" ::: "memory")
#define CP_WAIT1()  asm volatile("cp.async.wait_group 1;\n" ::: "memory")

__global__ void prep_kernel(
    const float* __restrict__ in_bn,
    const float* __restrict__ sh_b0, const float* __restrict__ sh_bn0,
    const float* __restrict__ sh_b1, const float* __restrict__ sh_bn1,
    const float* __restrict__ init_b, const float* __restrict__ init_bn,
    const float* __restrict__ step_b, const float* __restrict__ step_bn,
    const float* __restrict__ att_b,  const float* __restrict__ att_bn)
{
    int idx = blockIdx.x * blockDim.x + threadIdx.x;
    if (idx >= AC_TOTAL) return;
    float s, bb, m, v, bias;
    if (idx < OFF_SH0) {
        int c = idx;
        s = in_bn[c]; bb = in_bn[320 + c]; m = in_bn[640 + c]; v = in_bn[960 + c];
        bias = 0.f;
    } else if (idx < OFF_SH1) {
        int c = idx - OFF_SH0;
        s = sh_bn0[c]; bb = sh_bn0[256 + c]; m = sh_bn0[512 + c]; v = sh_bn0[768 + c];
        bias = sh_b0[c];
    } else if (idx < OFF_INIT) {
        int c = idx - OFF_SH1;
        s = sh_bn1[c]; bb = sh_bn1[256 + c]; m = sh_bn1[512 + c]; v = sh_bn1[768 + c];
        bias = sh_b1[c];
    } else if (idx < OFF_STEP) {
        int q = (idx - OFF_INIT) >> 8;
        int c = (idx - OFF_INIT) & 255;
        const float* p = init_bn + q * 1024;
        s = p[c]; bb = p[256 + c]; m = p[512 + c]; v = p[768 + c];
        bias = init_b[q * 256 + c];
    } else if (idx < OFF_ATT) {
        int q = (idx - OFF_STEP) >> 8;
        int c = (idx - OFF_STEP) & 255;
        const float* p = step_bn + q * 1024;
        s = p[c]; bb = p[256 + c]; m = p[512 + c]; v = p[768 + c];
        bias = step_b[q * 256 + c];
    } else {
        int q = (idx - OFF_ATT) / 80;
        int c = (idx - OFF_ATT) % 80;
        const float* p = att_bn + q * 320;
        s = p[c]; bb = p[80 + c]; m = p[160 + c]; v = p[240 + c];
        bias = att_b[q * 80 + c];
    }
    float A = s * rsqrtf(v + 1e-5f);
    g_A[idx] = A;
    g_C[idx] = (bias - m) * A + bb;
}

// One fused GLU layer: dst[:,j] = GLU(BN(src @ W + b)) [+ residual]
// src/dst are smem, column-major [col][64] with XOR swizzle SWZ.
// 512 threads; thread t: rows r0..r0+3, GLU cols c4..c4+3 (o) / +128 (g).
// Warp = 4 row-groups x 8 col-groups: each W address shared by 4 lanes
// (1 wavefront per W LDS.128), x broadcast 8-way (1 wavefront).
// Weights pipelined via cp.async in 16-k chunks through a 3-buffer ring.
template<bool USE_MASK, bool RESID>
__device__ __forceinline__ void glu_layer(
    int K, const float* __restrict__ Wg, int acoff,
    const float* src, float* dst, float* ws, unsigned ws_s, const float* mg,
    int t, int r0, int c4)
{
    unsigned long long acc[4][4];   // [row][pair]: 0,1 = o cols, 2,3 = g cols
#pragma unroll
    for (int i = 0; i < 4; i++)
#pragma unroll
        for (int j = 0; j < 4; j++) acc[i][j] = 0ull;

    const int nch = K >> 4;     // 16-k chunks, 4096 floats = 1024 float4

    // prologue: stage chunks 0 and 1 (2 float4 per thread per chunk)
    {
        const float* s0 = Wg + t * 4;
        cp16(ws_s + t * 16, s0);
        cp16(ws_s + (t + 512) * 16, s0 + 2048);
        CP_COMMIT();
        if (nch > 1) {
            const float* s1 = Wg + 4096 + t * 4;
            cp16(ws_s + 16384 + t * 16, s1);
            cp16(ws_s + 16384 + (t + 512) * 16, s1 + 2048);
            CP_COMMIT();
        }
    }

    for (int c = 0; c < nch; c++) {
        if (c + 1 < nch) CP_WAIT1(); else CP_WAIT0();
        __syncthreads();
        if (c + 2 < nch) {
            int b = (c + 2) % 3;
            const float* sp = Wg + (c + 2) * 4096 + t * 4;
            cp16(ws_s + b * 16384 + t * 16, sp);
            cp16(ws_s + b * 16384 + (t + 512) * 16, sp + 2048);
            CP_COMMIT();
        }
        const float* buf = ws + (c % 3) * 4096;

        float4 mvec;
        if (USE_MASK && c >= 4) {   // k >= 64: group constant within 16-k chunk
            int g = 60 + c;
            mvec = *(const float4*)(mg + g * 64 + (r0 ^ (g & 0x1C)));
        }
#pragma unroll 8
        for (int ki = 0; ki < 16; ki++) {
            int k = c * 16 + ki;
            float4 xv = *(const float4*)(src + k * 64 + (r0 ^ (k & 0x1C)));
            if (USE_MASK) {
                if (c >= 4) {
                    xv.x *= mvec.x; xv.y *= mvec.y; xv.z *= mvec.z; xv.w *= mvec.w;
                } else {
                    float4 mv = *(const float4*)(mg + k * 64 + (r0 ^ (k & 0x1C)));
                    xv.x *= mv.x; xv.y *= mv.y; xv.z *= mv.z; xv.w *= mv.w;
                }
            }
            unsigned long long xd[4];
            PACKDUP(xd[0], xv.x);
            PACKDUP(xd[1], xv.y);
            PACKDUP(xd[2], xv.z);
            PACKDUP(xd[3], xv.w);

            const float* wr = buf + ki * 256 + c4;
            ulonglong2 wo = *(const ulonglong2*)(wr);        // o cols c4..c4+3
            ulonglong2 wg = *(const ulonglong2*)(wr + 128);  // g cols
            unsigned long long wp[4] = {wo.x, wo.y, wg.x, wg.y};
#pragma unroll
            for (int rr = 0; rr < 4; rr++)
#pragma unroll
                for (int j = 0; j < 4; j++)
                    FMA2(acc[rr][j], xd[rr], wp[j]);
        }
    }
    __syncthreads();

    // epilogue: BN fold + GLU + optional residual
    float ov[4][4], gv[4][4];   // [row][local col]
#pragma unroll
    for (int rr = 0; rr < 4; rr++)
#pragma unroll
        for (int j = 0; j < 2; j++) {
            UNPACK2(ov[rr][j * 2], ov[rr][j * 2 + 1], acc[rr][j]);
            UNPACK2(gv[rr][j * 2], gv[rr][j * 2 + 1], acc[rr][2 + j]);
        }

#pragma unroll
    for (int i = 0; i < 4; i++) {
        int col = c4 + i;               // GLU col 0..127
        float Ao = g_A[acoff + col],       Co = g_C[acoff + col];
        float Ag = g_A[acoff + 128 + col], Cg = g_C[acoff + 128 + col];
        float y[4];
#pragma unroll
        for (int rr = 0; rr < 4; rr++) {
            float oo = fmaf(ov[rr][i], Ao, Co);
            float gg = fmaf(gv[rr][i], Ag, Cg);
            float sg = 1.f / (1.f + __expf(-gg));
            y[rr] = oo * sg;
        }
        float* dp = dst + col * 64 + (r0 ^ (col & 0x1C));
        if (RESID) {
            float4 old = *(float4*)dp;
            y[0] = (old.x + y[0]) * RES_SCALE;
            y[1] = (old.y + y[1]) * RES_SCALE;
            y[2] = (old.z + y[2]) * RES_SCALE;
            y[3] = (old.w + y[3]) * RES_SCALE;
        }
        *(float4*)dp = make_float4(y[0], y[1], y[2], y[3]);
    }
    __syncthreads();
}

__global__ void __launch_bounds__(NTH, 1) tabnet_kernel(
    const float* __restrict__ x_num, const int* __restrict__ x_cat,
    const float* __restrict__ emb_W,
    const float* __restrict__ sh_W0, const float* __restrict__ sh_W1,
    const float* __restrict__ init_W, const float* __restrict__ step_W,
    const float* __restrict__ att_W, const float* __restrict__ out_W,
    const float* __restrict__ out_b, float* __restrict__ out)
{
    extern __shared__ float sm[];
    float* xs = sm;                 // [320][64] swizzled
    float* hs = xs + 320 * 64;      // [128][64] swizzled
    float* ws = hs + 128 * 64;      // 12288 floats: 3 cp.async bufs / att stage / logits
    float* mg = ws + 12288;         // [80][64]  mask per group, swizzled
    float* pr = mg + 80 * 64;       // [64][80]  prior, row-major
    float* ds = pr + 64 * 80;       // [64][64]  decision sum (phys copy of hs layout)

    const int t    = threadIdx.x;
    const int w    = t >> 5;
    const int lane = t & 31;
    // warp = 4 row-groups x 8 col-groups: 4-way W sharing, 8-way x broadcast
    const int r0 = ((w & 3) << 4) + ((lane >> 3) << 2);   // 0..60 step 4
    const int c4 = ((w >> 2) << 5) + ((lane & 7) << 2);   // 0..124 step 4
    const int rowb = blockIdx.x * TM;
    const unsigned ws_s = (unsigned)__cvta_generic_to_shared(ws);

    // ---- load x_num with folded input BN ----
#pragma unroll
    for (int i = 0; i < 8; i++) {
        int idx = t + i * 512;          // 4096 elems
        int r = idx & 63, f = idx >> 6;
        xs[SWZ(f, r)] = x_num[(rowb + r) * 64 + f] * g_A[f] + g_C[f];
    }
    // ---- embeddings (16 cats x 16 dims) with folded input BN ----
#pragma unroll
    for (int i = 0; i < 2; i++) {
        int p = t + i * 512;            // 1024 (row,cat) pairs
        int r = p & 63, c = p >> 6;
        int id = x_cat[(rowb + r) * 16 + c];
        const float* e = emb_W + (c * 1000 + id) * 16;
#pragma unroll
        for (int j = 0; j < 16; j++) {
            int f = 64 + c * 16 + j;
            xs[SWZ(f, r)] = e[j] * g_A[f] + g_C[f];
        }
    }
    for (int i = t; i < 80 * 64; i += NTH) mg[i] = 1.f;
    for (int i = t; i < 64 * 80; i += NTH) pr[i] = 1.f;
    for (int i = t; i < 64 * 64; i += NTH) ds[i] = 0.f;
    __syncthreads();

    // ---- init pass: ft_shared + ft_indep(init) ----
    glu_layer<true,  false>(320, sh_W0, OFF_SH0, xs, hs, ws, ws_s, mg, t, r0, c4);
    glu_layer<false, true >(128, sh_W1, OFF_SH1, hs, hs, ws, ws_s, mg, t, r0, c4);
    glu_layer<false, true >(128, init_W,             OFF_INIT,       hs, hs, ws, ws_s, mg, t, r0, c4);
    glu_layer<false, true >(128, init_W + 128 * 256, OFF_INIT + 256, hs, hs, ws, ws_s, mg, t, r0, c4);

    for (int s = 0; s < 5; s++) {
        // ---- attention GEMM: logits = BN(a @ att_W[s] + b) * prior ----
        const float* aw = att_W + s * 64 * 80;
        for (int i = t; i < 5120; i += NTH) ws[i] = aw[i];
        __syncthreads();

        float acc[4][5];
        const int ra = ((t & 255) >> 4) << 2;   // rows 0..60 step 4
        const int c5 = (t & 15) * 5;
        if (t < 256) {
#pragma unroll
            for (int rr = 0; rr < 4; rr++)
#pragma unroll
                for (int j = 0; j < 5; j++) acc[rr][j] = 0.f;
#pragma unroll 4
            for (int kk = 0; kk < 64; kk++) {
                int col = 64 + kk;
                float4 av = *(const float4*)(hs + col * 64 + (ra ^ (col & 0x1C)));
                float arr[4] = {av.x, av.y, av.z, av.w};
#pragma unroll
                for (int j = 0; j < 5; j++) {
                    float wv = ws[kk * 80 + c5 + j];
#pragma unroll
                    for (int rr = 0; rr < 4; rr++)
                        acc[rr][j] = fmaf(arr[rr], wv, acc[rr][j]);
                }
            }
        }
        __syncthreads();

        // write logits (BN-folded * prior) into ws as [row][80]
        if (t < 256) {
#pragma unroll
            for (int j = 0; j < 5; j++) {
                int g = c5 + j;
                float A = g_A[OFF_ATT + s * 80 + g], C = g_C[OFF_ATT + s * 80 + g];
#pragma unroll
                for (int rr = 0; rr < 4; rr++) {
                    int r = ra + rr;
                    ws[r * 80 + g] = fmaf(acc[rr][j], A, C) * pr[r * 80 + g];
                }
            }
        }
        __syncthreads();

        // ---- sparsemax via Michelot's exact simplex projection ----
        if (t < 64) {
            const float* z = ws + t * 80;
            float S = 0.f;
            for (int i = 0; i < 80; i++) S += z[i];
            int k = 80;
            float tau = (S - 1.f) / 80.f;
            for (int it = 0; it < 80; it++) {
                float S2 = 0.f; int k2 = 0;
                for (int i = 0; i < 80; i++) {
                    float zi = z[i];
                    if (zi > tau) { S2 += zi; k2++; }
                }
                if (k2 == k) break;
                k = k2;
                tau = (S2 - 1.f) / (float)k2;
            }
            for (int g = 0; g < 80; g++) {
                float m_ = z[g] - tau;
                m_ = m_ > 0.f ? m_ : 0.f;
                mg[SWZ(g, t)] = m_;
                pr[t * 80 + g] *= (GAMMA_C - m_);
            }
        }
        __syncthreads();

        // ---- masked ft pass: ft_shared(mask*x) -> ft_indep(step s) ----
        const float* sw = step_W + s * 2 * 128 * 256;
        glu_layer<true,  false>(320, sh_W0, OFF_SH0, xs, hs, ws, ws_s, mg, t, r0, c4);
        glu_layer<false, true >(128, sh_W1, OFF_SH1, hs, hs, ws, ws_s, mg, t, r0, c4);
        glu_layer<false, true >(128, sw,             OFF_STEP + (s * 2) * 256,     hs, hs, ws, ws_s, mg, t, r0, c4);
        glu_layer<false, true >(128, sw + 128 * 256, OFF_STEP + (s * 2 + 1) * 256, hs, hs, ws, ws_s, mg, t, r0, c4);

        // ---- decision_sum += relu(d) (d = hs cols 0..63; same phys layout) ----
#pragma unroll
        for (int i = 0; i < 8; i++) {
            int idx = t + i * 512;      // 4096 elems
            float v = hs[idx];
            ds[idx] += v > 0.f ? v : 0.f;
        }
        __syncthreads();
    }

    // ---- final: out = decision_sum @ out_W + out_b ----
    if (t < 64) {
        float sacc = 0.f;
#pragma unroll
        for (int j = 0; j < 64; j++)
            sacc = fmaf(ds[SWZ(j, t)], out_W[j], sacc);
        out[rowb + t] = sacc + out_b[0];
    }
}

#define SMEM_FLOATS (320*64 + 128*64 + 12288 + 80*64 + 64*80 + 64*64)
#define SMEM_BYTES  (SMEM_FLOATS * 4)

extern "C" void kernel_launch(void* const* d_in, const int* in_sizes, int n_in,
                              void* d_out, int out_size)
{
    const float* x_num   = (const float*)d_in[0];
    const int*   x_cat   = (const int*)  d_in[1];
    const float* emb_W   = (const float*)d_in[2];
    const float* in_bn   = (const float*)d_in[3];
    const float* sh_W0   = (const float*)d_in[4];
    const float* sh_b0   = (const float*)d_in[5];
    const float* sh_bn0  = (const float*)d_in[6];
    const float* sh_W1   = (const float*)d_in[7];
    const float* sh_b1   = (const float*)d_in[8];
    const float* sh_bn1  = (const float*)d_in[9];
    const float* init_W  = (const float*)d_in[10];
    const float* init_b  = (const float*)d_in[11];
    const float* init_bn = (const float*)d_in[12];
    const float* step_W  = (const float*)d_in[13];
    const float* step_b  = (const float*)d_in[14];
    const float* step_bn = (const float*)d_in[15];
    const float* att_W   = (const float*)d_in[16];
    const float* att_b   = (const float*)d_in[17];
    const float* att_bn  = (const float*)d_in[18];
    const float* out_W   = (const float*)d_in[19];
    const float* out_b   = (const float*)d_in[20];
    float* out = (float*)d_out;

    cudaFuncSetAttribute(tabnet_kernel,
                         cudaFuncAttributeMaxDynamicSharedMemorySize, SMEM_BYTES);

    prep_kernel<<<(AC_TOTAL + 255) / 256, 256>>>(
        in_bn, sh_b0, sh_bn0, sh_b1, sh_bn1,
        init_b, init_bn, step_b, step_bn, att_b, att_bn);

    tabnet_kernel<<<BATCH / TM, NTH, SMEM_BYTES>>>(
        x_num, x_cat, emb_W, sh_W0, sh_W1, init_W, step_W,
        att_W, out_W, out_b, out);
}

// round 12
// speedup vs baseline: 1.0008x; 1.0008x over previous
#include <cuda_runtime.h>

#define BATCH     65536
#define TM        64
#define NTH       512
#define RES_SCALE 0.70710678118654752440f
#define GAMMA_C   1.5f

// folded BN affine tables: y = acc*A + C
#define OFF_IN    0
#define OFF_SH0   320
#define OFF_SH1   576
#define OFF_INIT  832
#define OFF_STEP  1344
#define OFF_ATT   3904
#define AC_TOTAL  4304

__device__ float g_A[AC_TOTAL];
__device__ float g_C[AC_TOTAL];

// activation layout: element (col, r) -> col*64 + (r ^ (col & 0x1C))
#define SWZ(col, r) ((col) * 64 + ((r) ^ ((col) & 0x1C)))

#define FMA2(acc, a, b) \
    asm("fma.rn.f32x2 %0, %1, %2, %0;" : "+l"(acc) : "l"(a), "l"(b))
#define PACKDUP(dst, v) \
    asm("mov.b64 %0, {%1, %1};" : "=l"(dst) : "r"(__float_as_uint(v)))
#define UNPACK2(lo, hi, v) \
    asm("mov.b64 {%0, %1}, %2;" : "=f"(lo), "=f"(hi) : "l"(v))

__device__ __forceinline__ void cp16(unsigned dst, const float* src) {
    asm volatile("cp.async.ca.shared.global [%0], [%1], 16;\n"
                 :: "r"(dst), "l"(src));
}
#define CP_COMMIT() asm volatile("cp.async.commit_group;\n" ::: "memory")
#define CP_WAIT0()  asm volatile("cp.async.wait_group 0;\n" ::: "memory")
#define CP_WAIT1()  asm volatile("cp.async.wait_group 1;\n" ::: "memory")

__global__ void prep_kernel(
    const float* __restrict__ in_bn,
    const float* __restrict__ sh_b0, const float* __restrict__ sh_bn0,
    const float* __restrict__ sh_b1, const float* __restrict__ sh_bn1,
    const float* __restrict__ init_b, const float* __restrict__ init_bn,
    const float* __restrict__ step_b, const float* __restrict__ step_bn,
    const float* __restrict__ att_b,  const float* __restrict__ att_bn)
{
    int idx = blockIdx.x * blockDim.x + threadIdx.x;
    if (idx >= AC_TOTAL) return;
    float s, bb, m, v, bias;
    if (idx < OFF_SH0) {
        int c = idx;
        s = in_bn[c]; bb = in_bn[320 + c]; m = in_bn[640 + c]; v = in_bn[960 + c];
        bias = 0.f;
    } else if (idx < OFF_SH1) {
        int c = idx - OFF_SH0;
        s = sh_bn0[c]; bb = sh_bn0[256 + c]; m = sh_bn0[512 + c]; v = sh_bn0[768 + c];
        bias = sh_b0[c];
    } else if (idx < OFF_INIT) {
        int c = idx - OFF_SH1;
        s = sh_bn1[c]; bb = sh_bn1[256 + c]; m = sh_bn1[512 + c]; v = sh_bn1[768 + c];
        bias = sh_b1[c];
    } else if (idx < OFF_STEP) {
        int q = (idx - OFF_INIT) >> 8;
        int c = (idx - OFF_INIT) & 255;
        const float* p = init_bn + q * 1024;
        s = p[c]; bb = p[256 + c]; m = p[512 + c]; v = p[768 + c];
        bias = init_b[q * 256 + c];
    } else if (idx < OFF_ATT) {
        int q = (idx - OFF_STEP) >> 8;
        int c = (idx - OFF_STEP) & 255;
        const float* p = step_bn + q * 1024;
        s = p[c]; bb = p[256 + c]; m = p[512 + c]; v = p[768 + c];
        bias = step_b[q * 256 + c];
    } else {
        int q = (idx - OFF_ATT) / 80;
        int c = (idx - OFF_ATT) % 80;
        const float* p = att_bn + q * 320;
        s = p[c]; bb = p[80 + c]; m = p[160 + c]; v = p[240 + c];
        bias = att_b[q * 80 + c];
    }
    float A = s * rsqrtf(v + 1e-5f);
    g_A[idx] = A;
    g_C[idx] = (bias - m) * A + bb;
}

// One fused GLU layer: dst[:,j] = GLU(BN(src @ W + b)) [+ residual]
// src/dst are smem, column-major [col][64] with XOR swizzle SWZ.
// 512 threads; thread t: rows r0..r0+3, GLU cols c4..c4+3 (o) / +128 (g).
// Warp = 4 row-groups x 8 col-groups: each W address shared by 4 lanes
// (1 wavefront per W LDS.128), x broadcast 8-way (1 wavefront).
// Weights pipelined via cp.async in 16-k chunks through a 3-buffer ring.
template<bool USE_MASK, bool RESID>
__device__ __forceinline__ void glu_layer(
    int K, const float* __restrict__ Wg, int acoff,
    const float* src, float* dst, float* ws, unsigned ws_s, const float* mg,
    int t, int r0, int c4)
{
    unsigned long long acc[4][4];   // [row][pair]: 0,1 = o cols, 2,3 = g cols
#pragma unroll
    for (int i = 0; i < 4; i++)
#pragma unroll
        for (int j = 0; j < 4; j++) acc[i][j] = 0ull;

    const int nch = K >> 4;     // 16-k chunks, 4096 floats = 1024 float4

    // prologue: stage chunks 0 and 1 (2 float4 per thread per chunk)
    {
        const float* s0 = Wg + t * 4;
        cp16(ws_s + t * 16, s0);
        cp16(ws_s + (t + 512) * 16, s0 + 2048);
        CP_COMMIT();
        if (nch > 1) {
            const float* s1 = Wg + 4096 + t * 4;
            cp16(ws_s + 16384 + t * 16, s1);
            cp16(ws_s + 16384 + (t + 512) * 16, s1 + 2048);
            CP_COMMIT();
        }
    }

    for (int c = 0; c < nch; c++) {
        if (c + 1 < nch) CP_WAIT1(); else CP_WAIT0();
        __syncthreads();
        if (c + 2 < nch) {
            int b = (c + 2) % 3;
            const float* sp = Wg + (c + 2) * 4096 + t * 4;
            cp16(ws_s + b * 16384 + t * 16, sp);
            cp16(ws_s + b * 16384 + (t + 512) * 16, sp + 2048);
            CP_COMMIT();
        }
        const float* buf = ws + (c % 3) * 4096;

        float4 mvec;
        if (USE_MASK && c >= 4) {   // k >= 64: group constant within 16-k chunk
            int g = 60 + c;
            mvec = *(const float4*)(mg + g * 64 + (r0 ^ (g & 0x1C)));
        }
#pragma unroll 8
        for (int ki = 0; ki < 16; ki++) {
            int k = c * 16 + ki;
            float4 xv = *(const float4*)(src + k * 64 + (r0 ^ (k & 0x1C)));
            if (USE_MASK) {
                if (c >= 4) {
                    xv.x *= mvec.x; xv.y *= mvec.y; xv.z *= mvec.z; xv.w *= mvec.w;
                } else {
                    float4 mv = *(const float4*)(mg + k * 64 + (r0 ^ (k & 0x1C)));
                    xv.x *= mv.x; xv.y *= mv.y; xv.z *= mv.z; xv.w *= mv.w;
                }
            }
            unsigned long long xd[4];
            PACKDUP(xd[0], xv.x);
            PACKDUP(xd[1], xv.y);
            PACKDUP(xd[2], xv.z);
            PACKDUP(xd[3], xv.w);

            const float* wr = buf + ki * 256 + c4;
            ulonglong2 wo = *(const ulonglong2*)(wr);        // o cols c4..c4+3
            ulonglong2 wg = *(const ulonglong2*)(wr + 128);  // g cols
            unsigned long long wp[4] = {wo.x, wo.y, wg.x, wg.y};
#pragma unroll
            for (int rr = 0; rr < 4; rr++)
#pragma unroll
                for (int j = 0; j < 4; j++)
                    FMA2(acc[rr][j], xd[rr], wp[j]);
        }
    }
    __syncthreads();

    // epilogue: BN fold + GLU + optional residual
    float ov[4][4], gv[4][4];   // [row][local col]
#pragma unroll
    for (int rr = 0; rr < 4; rr++)
#pragma unroll
        for (int j = 0; j < 2; j++) {
            UNPACK2(ov[rr][j * 2], ov[rr][j * 2 + 1], acc[rr][j]);
            UNPACK2(gv[rr][j * 2], gv[rr][j * 2 + 1], acc[rr][2 + j]);
        }

#pragma unroll
    for (int i = 0; i < 4; i++) {
        int col = c4 + i;               // GLU col 0..127
        float Ao = g_A[acoff + col],       Co = g_C[acoff + col];
        float Ag = g_A[acoff + 128 + col], Cg = g_C[acoff + 128 + col];
        float y[4];
#pragma unroll
        for (int rr = 0; rr < 4; rr++) {
            float oo = fmaf(ov[rr][i], Ao, Co);
            float gg = fmaf(gv[rr][i], Ag, Cg);
            float sg = 1.f / (1.f + __expf(-gg));
            y[rr] = oo * sg;
        }
        float* dp = dst + col * 64 + (r0 ^ (col & 0x1C));
        if (RESID) {
            float4 old = *(float4*)dp;
            y[0] = (old.x + y[0]) * RES_SCALE;
            y[1] = (old.y + y[1]) * RES_SCALE;
            y[2] = (old.z + y[2]) * RES_SCALE;
            y[3] = (old.w + y[3]) * RES_SCALE;
        }
        *(float4*)dp = make_float4(y[0], y[1], y[2], y[3]);
    }
    __syncthreads();
}

__global__ void __launch_bounds__(NTH, 1) tabnet_kernel(
    const float* __restrict__ x_num, const int* __restrict__ x_cat,
    const float* __restrict__ emb_W,
    const float* __restrict__ sh_W0, const float* __restrict__ sh_W1,
    const float* __restrict__ init_W, const float* __restrict__ step_W,
    const float* __restrict__ att_W, const float* __restrict__ out_W,
    const float* __restrict__ out_b, float* __restrict__ out)
{
    extern __shared__ float sm[];
    float* xs = sm;                 // [320][64] swizzled
    float* hs = xs + 320 * 64;      // [128][64] swizzled
    float* ws = hs + 128 * 64;      // 12288 floats: 3 cp.async bufs / att stage / logits
    float* mg = ws + 12288;         // [80][64]  mask per group, swizzled
    float* pr = mg + 80 * 64;       // [64][80]  prior, row-major
    float* ds = pr + 64 * 80;       // [64][64]  decision sum (phys copy of hs layout)

    const int t    = threadIdx.x;
    const int w    = t >> 5;
    const int lane = t & 31;
    // warp = 4 row-groups x 8 col-groups: 4-way W sharing, 8-way x broadcast
    const int r0 = ((w & 3) << 4) + ((lane >> 3) << 2);   // 0..60 step 4
    const int c4 = ((w >> 2) << 5) + ((lane & 7) << 2);   // 0..124 step 4
    const int rowb = blockIdx.x * TM;
    const unsigned ws_s = (unsigned)__cvta_generic_to_shared(ws);

    // ---- load x_num with folded input BN ----
#pragma unroll
    for (int i = 0; i < 8; i++) {
        int idx = t + i * 512;          // 4096 elems
        int r = idx & 63, f = idx >> 6;
        xs[SWZ(f, r)] = x_num[(rowb + r) * 64 + f] * g_A[f] + g_C[f];
    }
    // ---- embeddings (16 cats x 16 dims) with folded input BN ----
#pragma unroll
    for (int i = 0; i < 2; i++) {
        int p = t + i * 512;            // 1024 (row,cat) pairs
        int r = p & 63, c = p >> 6;
        int id = x_cat[(rowb + r) * 16 + c];
        const float* e = emb_W + (c * 1000 + id) * 16;
#pragma unroll
        for (int j = 0; j < 16; j++) {
            int f = 64 + c * 16 + j;
            xs[SWZ(f, r)] = e[j] * g_A[f] + g_C[f];
        }
    }
    for (int i = t; i < 80 * 64; i += NTH) mg[i] = 1.f;
    for (int i = t; i < 64 * 80; i += NTH) pr[i] = 1.f;
    for (int i = t; i < 64 * 64; i += NTH) ds[i] = 0.f;
    __syncthreads();

    // ---- init pass: ft_shared + ft_indep(init) ----
    glu_layer<true,  false>(320, sh_W0, OFF_SH0, xs, hs, ws, ws_s, mg, t, r0, c4);
    glu_layer<false, true >(128, sh_W1, OFF_SH1, hs, hs, ws, ws_s, mg, t, r0, c4);
    glu_layer<false, true >(128, init_W,             OFF_INIT,       hs, hs, ws, ws_s, mg, t, r0, c4);
    glu_layer<false, true >(128, init_W + 128 * 256, OFF_INIT + 256, hs, hs, ws, ws_s, mg, t, r0, c4);

    for (int s = 0; s < 5; s++) {
        // ---- attention GEMM: logits = BN(a @ att_W[s] + b) * prior ----
        const float* aw = att_W + s * 64 * 80;
        for (int i = t; i < 5120; i += NTH) ws[i] = aw[i];
        __syncthreads();

        float acc[4][5];
        const int ra = ((t & 255) >> 4) << 2;   // rows 0..60 step 4
        const int c5 = (t & 15) * 5;
        if (t < 256) {
#pragma unroll
            for (int rr = 0; rr < 4; rr++)
#pragma unroll
                for (int j = 0; j < 5; j++) acc[rr][j] = 0.f;
#pragma unroll 4
            for (int kk = 0; kk < 64; kk++) {
                int col = 64 + kk;
                float4 av = *(const float4*)(hs + col * 64 + (ra ^ (col & 0x1C)));
                float arr[4] = {av.x, av.y, av.z, av.w};
#pragma unroll
                for (int j = 0; j < 5; j++) {
                    float wv = ws[kk * 80 + c5 + j];
#pragma unroll
                    for (int rr = 0; rr < 4; rr++)
                        acc[rr][j] = fmaf(arr[rr], wv, acc[rr][j]);
                }
            }
        }
        __syncthreads();

        // write logits (BN-folded * prior) into ws as [row][80]
        if (t < 256) {
#pragma unroll
            for (int j = 0; j < 5; j++) {
                int g = c5 + j;
                float A = g_A[OFF_ATT + s * 80 + g], C = g_C[OFF_ATT + s * 80 + g];
#pragma unroll
                for (int rr = 0; rr < 4; rr++) {
                    int r = ra + rr;
                    ws[r * 80 + g] = fmaf(acc[rr][j], A, C) * pr[r * 80 + g];
                }
            }
        }
        __syncthreads();

        // ---- sparsemax via Michelot's exact simplex projection ----
        if (t < 64) {
            const float* z = ws + t * 80;
            float S = 0.f;
            for (int i = 0; i < 80; i++) S += z[i];
            int k = 80;
            float tau = (S - 1.f) / 80.f;
            for (int it = 0; it < 80; it++) {
                float S2 = 0.f; int k2 = 0;
                for (int i = 0; i < 80; i++) {
                    float zi = z[i];
                    if (zi > tau) { S2 += zi; k2++; }
                }
                if (k2 == k) break;
                k = k2;
                tau = (S2 - 1.f) / (float)k2;
            }
            for (int g = 0; g < 80; g++) {
                float m_ = z[g] - tau;
                m_ = m_ > 0.f ? m_ : 0.f;
                mg[SWZ(g, t)] = m_;
                pr[t * 80 + g] *= (GAMMA_C - m_);
            }
        }
        __syncthreads();

        // ---- masked ft pass: ft_shared(mask*x) -> ft_indep(step s) ----
        const float* sw = step_W + s * 2 * 128 * 256;
        glu_layer<true,  false>(320, sh_W0, OFF_SH0, xs, hs, ws, ws_s, mg, t, r0, c4);
        glu_layer<false, true >(128, sh_W1, OFF_SH1, hs, hs, ws, ws_s, mg, t, r0, c4);
        glu_layer<false, true >(128, sw,             OFF_STEP + (s * 2) * 256,     hs, hs, ws, ws_s, mg, t, r0, c4);
        glu_layer<false, true >(128, sw + 128 * 256, OFF_STEP + (s * 2 + 1) * 256, hs, hs, ws, ws_s, mg, t, r0, c4);

        // ---- decision_sum += relu(d) (d = hs cols 0..63; same phys layout) ----
#pragma unroll
        for (int i = 0; i < 8; i++) {
            int idx = t + i * 512;      // 4096 elems
            float v = hs[idx];
            ds[idx] += v > 0.f ? v : 0.f;
        }
        __syncthreads();
    }

    // ---- final: out = decision_sum @ out_W + out_b ----
    if (t < 64) {
        float sacc = 0.f;
#pragma unroll
        for (int j = 0; j < 64; j++)
            sacc = fmaf(ds[SWZ(j, t)], out_W[j], sacc);
        out[rowb + t] = sacc + out_b[0];
    }
}

#define SMEM_FLOATS (320*64 + 128*64 + 12288 + 80*64 + 64*80 + 64*64)
#define SMEM_BYTES  (SMEM_FLOATS * 4)

extern "C" void kernel_launch(void* const* d_in, const int* in_sizes, int n_in,
                              void* d_out, int out_size)
{
    const float* x_num   = (const float*)d_in[0];
    const int*   x_cat   = (const int*)  d_in[1];
    const float* emb_W   = (const float*)d_in[2];
    const float* in_bn   = (const float*)d_in[3];
    const float* sh_W0   = (const float*)d_in[4];
    const float* sh_b0   = (const float*)d_in[5];
    const float* sh_bn0  = (const float*)d_in[6];
    const float* sh_W1   = (const float*)d_in[7];
    const float* sh_b1   = (const float*)d_in[8];
    const float* sh_bn1  = (const float*)d_in[9];
    const float* init_W  = (const float*)d_in[10];
    const float* init_b  = (const float*)d_in[11];
    const float* init_bn = (const float*)d_in[12];
    const float* step_W  = (const float*)d_in[13];
    const float* step_b  = (const float*)d_in[14];
    const float* step_bn = (const float*)d_in[15];
    const float* att_W   = (const float*)d_in[16];
    const float* att_b   = (const float*)d_in[17];
    const float* att_bn  = (const float*)d_in[18];
    const float* out_W   = (const float*)d_in[19];
    const float* out_b   = (const float*)d_in[20];
    float* out = (float*)d_out;

    cudaFuncSetAttribute(tabnet_kernel,
                         cudaFuncAttributeMaxDynamicSharedMemorySize, SMEM_BYTES);

    prep_kernel<<<(AC_TOTAL + 255) / 256, 256>>>(
        in_bn, sh_b0, sh_bn0, sh_b1, sh_bn1,
        init_b, init_bn, step_b, step_bn, att_b, att_bn);

    tabnet_kernel<<<BATCH / TM, NTH, SMEM_BYTES>>>(
        x_num, x_cat, emb_W, sh_W0, sh_W1, init_W, step_W,
        att_W, out_W, out_b, out);
}

// round 14
// speedup vs baseline: 1.5922x; 1.5909x over previous
#include <cuda_runtime.h>
#include <cuda_bf16.h>
#include <stdint.h>

#define NTILES 1024
#define NTH    256
#define RES_SCALE 0.70710678118654752440f
#define GAMMA_C   1.5f

#define OFF_SH0   320
#define OFF_SH1   576
#define OFF_INIT  832
#define OFF_STEP  1344
#define OFF_ATT   3904
#define AC_TOTAL  4304

__device__ float g_A[AC_TOTAL];
__device__ float g_C[AC_TOTAL];
// W scratch: 62 chunks (32-k) x [hi: 256n x 32k][lo: 256n x 32k] bf16, n-major
__device__ __nv_bfloat16 w_scr[62 * 16384];
// x scratch: [tile][f 0..319][row 0..63] fp32, BN-folded
__device__ float xg[(size_t)NTILES * 20480];

#define SWZ(col, r) ((col) * 64 + ((r) ^ ((col) & 0x1C)))

// smem float offsets
#define S_A    0        // A hi [64r x 32k] bf16 padded 80B rows (5120B) + lo (5120B)
#define S_W    2560     // 2 bufs x (hi 20480B + lo 20480B); reused for attW+logits
#define S_XST  23040    // 2 x 2048 floats x stage
#define S_HS   27136    // hs [128 col][64 r] fp32, SWZ
#define S_MG   35328    // mask [80][64]
#define S_PR   40448    // prior [64][80]
#define S_DS   45568    // decision sum [64][64]
#define S_TOT  49664
#define SMEM_BYTES (S_TOT * 4)

__device__ __forceinline__ uint32_t smem_u32(const void* p) {
    uint32_t a;
    asm("{ .reg .u64 t; cvta.to.shared.u64 t, %1; cvt.u32.u64 %0, t; }"
        : "=r"(a) : "l"(p));
    return a;
}
__device__ __forceinline__ void cp16(unsigned dst, const void* src) {
    asm volatile("cp.async.ca.shared.global [%0], [%1], 16;" :: "r"(dst), "l"(src));
}
#define CP_COMMIT() asm volatile("cp.async.commit_group;" ::: "memory")
#define CP_WAIT0()  asm volatile("cp.async.wait_group 0;" ::: "memory")
#define CP_WAIT1()  asm volatile("cp.async.wait_group 1;" ::: "memory")

__device__ __forceinline__ void ldm_x4(uint32_t* r, uint32_t addr) {
    asm volatile("ldmatrix.sync.aligned.m8n8.x4.shared.b16 {%0,%1,%2,%3}, [%4];"
        : "=r"(r[0]), "=r"(r[1]), "=r"(r[2]), "=r"(r[3]) : "r"(addr));
}
__device__ __forceinline__ void mma_bf16(float* c, const uint32_t* a,
                                         uint32_t b0, uint32_t b1) {
    asm volatile(
        "mma.sync.aligned.m16n8k16.row.col.f32.bf16.bf16.f32 "
        "{%0,%1,%2,%3}, {%4,%5,%6,%7}, {%8,%9}, {%0,%1,%2,%3};"
        : "+f"(c[0]), "+f"(c[1]), "+f"(c[2]), "+f"(c[3])
        : "r"(a[0]), "r"(a[1]), "r"(a[2]), "r"(a[3]), "r"(b0), "r"(b1));
}

// ---------------- prep kernels ----------------
__global__ void prep_kernel(
    const float* __restrict__ in_bn,
    const float* __restrict__ sh_b0, const float* __restrict__ sh_bn0,
    const float* __restrict__ sh_b1, const float* __restrict__ sh_bn1,
    const float* __restrict__ init_b, const float* __restrict__ init_bn,
    const float* __restrict__ step_b, const float* __restrict__ step_bn,
    const float* __restrict__ att_b,  const float* __restrict__ att_bn)
{
    int idx = blockIdx.x * blockDim.x + threadIdx.x;
    if (idx >= AC_TOTAL) return;
    float s, bb, m, v, bias;
    if (idx < OFF_SH0) {
        int c = idx;
        s = in_bn[c]; bb = in_bn[320 + c]; m = in_bn[640 + c]; v = in_bn[960 + c];
        bias = 0.f;
    } else if (idx < OFF_SH1) {
        int c = idx - OFF_SH0;
        s = sh_bn0[c]; bb = sh_bn0[256 + c]; m = sh_bn0[512 + c]; v = sh_bn0[768 + c];
        bias = sh_b0[c];
    } else if (idx < OFF_INIT) {
        int c = idx - OFF_SH1;
        s = sh_bn1[c]; bb = sh_bn1[256 + c]; m = sh_bn1[512 + c]; v = sh_bn1[768 + c];
        bias = sh_b1[c];
    } else if (idx < OFF_STEP) {
        int q = (idx - OFF_INIT) >> 8, c = (idx - OFF_INIT) & 255;
        const float* p = init_bn + q * 1024;
        s = p[c]; bb = p[256 + c]; m = p[512 + c]; v = p[768 + c];
        bias = init_b[q * 256 + c];
    } else if (idx < OFF_ATT) {
        int q = (idx - OFF_STEP) >> 8, c = (idx - OFF_STEP) & 255;
        const float* p = step_bn + q * 1024;
        s = p[c]; bb = p[256 + c]; m = p[512 + c]; v = p[768 + c];
        bias = step_b[q * 256 + c];
    } else {
        int q = (idx - OFF_ATT) / 80, c = (idx - OFF_ATT) % 80;
        const float* p = att_bn + q * 320;
        s = p[c]; bb = p[80 + c]; m = p[160 + c]; v = p[240 + c];
        bias = att_b[q * 80 + c];
    }
    float A = s * rsqrtf(v + 1e-5f);
    g_A[idx] = A;
    g_C[idx] = (bias - m) * A + bb;
}

// transpose + hi/lo split weights into w_scr ([n][k] row-major per 32-k chunk)
__global__ void prep2_kernel(const float* __restrict__ sh_W0,
                             const float* __restrict__ sh_W1,
                             const float* __restrict__ init_W,
                             const float* __restrict__ step_W)
{
    int idx = blockIdx.x * blockDim.x + threadIdx.x;
    if (idx >= 62 * 8192) return;
    int c = idx >> 13, rem = idx & 8191;
    int n = rem >> 5, kin = rem & 31;
    const float* src; int kb;
    if (c < 10)      { src = sh_W0;            kb = c * 32; }
    else if (c < 14) { src = sh_W1;            kb = (c - 10) * 32; }
    else if (c < 18) { src = init_W;           kb = (c - 14) * 32; }
    else if (c < 22) { src = init_W + 128*256; kb = (c - 18) * 32; }
    else { int q = (c - 22) >> 2; src = step_W + q * 128 * 256;
           kb = ((c - 22) & 3) * 32; }
    float w = src[(kb + kin) * 256 + n];
    __nv_bfloat16 hi = __float2bfloat16(w);
    __nv_bfloat16 lo = __float2bfloat16(w - __bfloat162float(hi));
    w_scr[c * 16384 + n * 32 + kin]        = hi;
    w_scr[c * 16384 + 8192 + n * 32 + kin] = lo;
}

// BN-folded x, transposed: xg[tile][f][r]
__global__ void prep3_kernel(const float* __restrict__ x_num,
                             const int* __restrict__ x_cat,
                             const float* __restrict__ emb_W)
{
    long long idx = (long long)blockIdx.x * NTH + threadIdx.x;
    if (idx >= (long long)NTILES * 20480) return;
    int r = (int)(idx & 63);
    int f = (int)((idx >> 6) % 320);
    int tile = (int)(idx / 20480);
    int row = tile * 64 + r;
    float v;
    if (f < 64) v = x_num[row * 64 + f];
    else {
        int c = (f - 64) >> 4, j = (f - 64) & 15;
        v = emb_W[(c * 1000 + x_cat[row * 16 + c]) * 16 + j];
    }
    xg[idx] = v * g_A[f] + g_C[f];
}

// ---------------- staging helper ----------------
template<int MODE>
__device__ __forceinline__ void stage(int sub, int wc0, int tile,
                                      uint32_t smb, int t)
{
    int b = sub & 1;
    const __nv_bfloat16* wsrc = w_scr + (size_t)(wc0 + sub) * 16384;
    uint32_t wdst = smb + S_W * 4 + b * 40960;
#pragma unroll
    for (int i = 0; i < 8; i++) {
        int idx = t + i * 256;          // 0..2047 16B units
        int m = idx >> 10;              // 0 hi, 1 lo
        int rem = idx & 1023;
        int n = rem >> 2, k4 = rem & 3;
        cp16(wdst + m * 20480 + n * 80 + k4 * 16,
             wsrc + m * 8192 + n * 32 + k4 * 8);
    }
    if (MODE == 0) {
        const float* xsrc = xg + (size_t)tile * 20480 + sub * 2048;
        uint32_t xdst = smb + S_XST * 4 + b * 8192;
#pragma unroll
        for (int i = 0; i < 2; i++) {
            int idx = t + i * 256;
            cp16(xdst + idx * 16, xsrc + idx * 4);
        }
    }
    CP_COMMIT();
}

// ---------------- fused GLU layer via mma.sync ----------------
// MODE 0: A = mask * xg chunk; MODE 1: A = hs
template<int MODE, bool RESID>
__device__ void glu_mma(int nsub, int wc0, int acoff, int tile,
                        float* sm, uint32_t smb, int t)
{
    const int lane = t & 31, w = t >> 5;
    const int r0 = (w & 3) << 4;            // warp row base (of 64)
    const int cbase = (w >> 2) << 6;        // warp o-col base: 0 or 64
    const float* mg = sm + S_MG;
    const float* hs = sm + S_HS;

    float accO[8][4], accG[8][4];
#pragma unroll
    for (int j = 0; j < 8; j++)
#pragma unroll
        for (int e = 0; e < 4; e++) { accO[j][e] = 0.f; accG[j][e] = 0.f; }

    // lane-dependent ldmatrix address components (bytes)
    const uint32_t a_l = (uint32_t)(r0 + (lane & 7) + ((lane >> 3) & 1) * 8) * 80
                       + ((lane >> 4) * 8) * 2;
    const uint32_t b_l = (uint32_t)((lane & 7) + ((lane >> 4) & 1) * 8) * 80
                       + (((lane >> 3) & 1) * 8) * 2;

    stage<MODE>(0, wc0, tile, smb, t);
    stage<MODE>(1, wc0, tile, smb, t);

    for (int sub = 0; sub < nsub; sub++) {
        if (sub + 2 <= nsub) CP_WAIT1(); else CP_WAIT0();
        __syncthreads();

        // ---- convert A sub-tile to bf16 hi/lo (64r x 32k), padded 80B rows ----
        {
            const float* xst = sm + S_XST + (sub & 1) * 2048;
#pragma unroll
            for (int i = 0; i < 4; i++) {
                int el = t + i * 256;       // 1024 (r, kpair)
                int r = el & 63, kp = el >> 6, k = kp * 2;
                float x0, x1;
                if (MODE == 0) {
                    int kg = sub * 32 + k;
                    int g0 = kg < 64 ? kg : 64 + ((kg - 64) >> 4);
                    int g1 = (kg + 1) < 64 ? kg + 1 : 64 + ((kg - 63) >> 4);
                    x0 = xst[k * 64 + r] * mg[SWZ(g0, r)];
                    x1 = xst[(k + 1) * 64 + r] * mg[SWZ(g1, r)];
                } else {
                    x0 = hs[SWZ(sub * 32 + k, r)];
                    x1 = hs[SWZ(sub * 32 + k + 1, r)];
                }
                __nv_bfloat16 h0 = __float2bfloat16(x0);
                __nv_bfloat16 h1 = __float2bfloat16(x1);
                __nv_bfloat16 l0 = __float2bfloat16(x0 - __bfloat162float(h0));
                __nv_bfloat16 l1 = __float2bfloat16(x1 - __bfloat162float(h1));
                __nv_bfloat162 hp; hp.x = h0; hp.y = h1;
                __nv_bfloat162 lp; lp.x = l0; lp.y = l1;
                int off = r * 80 + k * 2;
                *(__nv_bfloat162*)((char*)sm + off) = hp;
                *(__nv_bfloat162*)((char*)sm + 5120 + off) = lp;
            }
        }
        __syncthreads();

        // ---- mma over 2 k16 steps ----
        const uint32_t wb = smb + S_W * 4 + (sub & 1) * 40960;
#pragma unroll
        for (int k16 = 0; k16 < 2; k16++) {
            uint32_t ah[4], al[4];
            ldm_x4(ah, smb + a_l + k16 * 32);
            ldm_x4(al, smb + 5120 + a_l + k16 * 32);
#pragma unroll
            for (int jp = 0; jp < 4; jp++) {
                uint32_t bh[4], bl[4];
                uint32_t nb = (uint32_t)(cbase + jp * 16) * 80 + b_l + k16 * 32;
                ldm_x4(bh, wb + nb);
                ldm_x4(bl, wb + 20480 + nb);
                mma_bf16(accO[2*jp],   ah, bh[0], bh[1]);
                mma_bf16(accO[2*jp+1], ah, bh[2], bh[3]);
                mma_bf16(accO[2*jp],   al, bh[0], bh[1]);
                mma_bf16(accO[2*jp+1], al, bh[2], bh[3]);
                mma_bf16(accO[2*jp],   ah, bl[0], bl[1]);
                mma_bf16(accO[2*jp+1], ah, bl[2], bl[3]);
            }
#pragma unroll
            for (int jp = 0; jp < 4; jp++) {
                uint32_t bh[4], bl[4];
                uint32_t nb = (uint32_t)(cbase + 128 + jp * 16) * 80 + b_l + k16 * 32;
                ldm_x4(bh, wb + nb);
                ldm_x4(bl, wb + 20480 + nb);
                mma_bf16(accG[2*jp],   ah, bh[0], bh[1]);
                mma_bf16(accG[2*jp+1], ah, bh[2], bh[3]);
                mma_bf16(accG[2*jp],   al, bh[0], bh[1]);
                mma_bf16(accG[2*jp+1], al, bh[2], bh[3]);
                mma_bf16(accG[2*jp],   ah, bl[0], bl[1]);
                mma_bf16(accG[2*jp+1], ah, bl[2], bl[3]);
            }
        }
        __syncthreads();
        if (sub + 2 < nsub) stage<MODE>(sub + 2, wc0, tile, smb, t);
    }

    // ---- epilogue: BN + GLU + residual, write hs ----
#pragma unroll
    for (int j = 0; j < 8; j++) {
        int colb = cbase + j * 8 + (lane & 3) * 2;
#pragma unroll
        for (int e = 0; e < 4; e++) {
            int row = r0 + (lane >> 2) + (e >> 1) * 8;
            int col = colb + (e & 1);
            float o = fmaf(accO[j][e], g_A[acoff + col], g_C[acoff + col]);
            float g = fmaf(accG[j][e], g_A[acoff + 128 + col],
                           g_C[acoff + 128 + col]);
            float y = o / (1.f + __expf(-g));
            float* hp = sm + S_HS + SWZ(col, row);
            if (RESID) y = (*hp + y) * RES_SCALE;
            *hp = y;
        }
    }
    __syncthreads();
}

// ---------------- main kernel ----------------
__global__ void __launch_bounds__(NTH, 1) tabnet_kernel(
    const float* __restrict__ att_W, const float* __restrict__ out_W,
    const float* __restrict__ out_b, float* __restrict__ out)
{
    extern __shared__ float sm[];
    const int t = threadIdx.x;
    const int tile = blockIdx.x;
    const uint32_t smb = smem_u32(sm);

    for (int i = t; i < 5120; i += NTH) sm[S_MG + i] = 1.f;
    for (int i = t; i < 5120; i += NTH) sm[S_PR + i] = 1.f;
    for (int i = t; i < 4096; i += NTH) sm[S_DS + i] = 0.f;
    __syncthreads();

    // ---- init pass ----
    glu_mma<0, false>(10, 0,  OFF_SH0,        tile, sm, smb, t);
    glu_mma<1, true >(4,  10, OFF_SH1,        tile, sm, smb, t);
    glu_mma<1, true >(4,  14, OFF_INIT,       tile, sm, smb, t);
    glu_mma<1, true >(4,  18, OFF_INIT + 256, tile, sm, smb, t);

    for (int s = 0; s < 5; s++) {
        // ---- attention: logits = BN(a @ att_W[s]) * prior ----
        float* wsW = sm + S_W;
        float* lg  = sm + S_W + 5120;
        float* pr  = sm + S_PR;
        float* mg  = sm + S_MG;
        const float* hs = sm + S_HS;
        const float* aw = att_W + s * 5120;
        for (int i = t; i < 5120; i += NTH) wsW[i] = aw[i];
        __syncthreads();

        {
            float acc[4][5];
            const int ra = (t >> 4) << 2;
            const int c5 = (t & 15) * 5;
#pragma unroll
            for (int rr = 0; rr < 4; rr++)
#pragma unroll
                for (int j = 0; j < 5; j++) acc[rr][j] = 0.f;
#pragma unroll 4
            for (int kk = 0; kk < 64; kk++) {
                int col = 64 + kk;
                float4 av = *(const float4*)(hs + col * 64 + (ra ^ (col & 0x1C)));
                float arr[4] = {av.x, av.y, av.z, av.w};
#pragma unroll
                for (int j = 0; j < 5; j++) {
                    float wv = wsW[kk * 80 + c5 + j];
#pragma unroll
                    for (int rr = 0; rr < 4; rr++)
                        acc[rr][j] = fmaf(arr[rr], wv, acc[rr][j]);
                }
            }
            __syncthreads();
#pragma unroll
            for (int j = 0; j < 5; j++) {
                int g = c5 + j;
                float A = g_A[OFF_ATT + s * 80 + g], C = g_C[OFF_ATT + s * 80 + g];
#pragma unroll
                for (int rr = 0; rr < 4; rr++) {
                    int r = ra + rr;
                    lg[r * 80 + g] = fmaf(acc[rr][j], A, C) * pr[r * 80 + g];
                }
            }
        }
        __syncthreads();

        // ---- sparsemax (Michelot) ----
        if (t < 64) {
            const float* z = lg + t * 80;
            float S = 0.f;
            for (int i = 0; i < 80; i++) S += z[i];
            int k = 80;
            float tau = (S - 1.f) / 80.f;
            for (int it = 0; it < 80; it++) {
                float S2 = 0.f; int k2 = 0;
                for (int i = 0; i < 80; i++) {
                    float zi = z[i];
                    if (zi > tau) { S2 += zi; k2++; }
                }
                if (k2 == k) break;
                k = k2;
                tau = (S2 - 1.f) / (float)k2;
            }
            for (int g = 0; g < 80; g++) {
                float m_ = z[g] - tau;
                m_ = m_ > 0.f ? m_ : 0.f;
                mg[SWZ(g, t)] = m_;
                pr[t * 80 + g] *= (GAMMA_C - m_);
            }
        }
        __syncthreads();

        // ---- masked ft pass ----
        glu_mma<0, false>(10, 0,      OFF_SH0,                  tile, sm, smb, t);
        glu_mma<1, true >(4,  10,     OFF_SH1,                  tile, sm, smb, t);
        glu_mma<1, true >(4,  22+8*s, OFF_STEP + (2*s) * 256,   tile, sm, smb, t);
        glu_mma<1, true >(4,  26+8*s, OFF_STEP + (2*s+1) * 256, tile, sm, smb, t);

        // ---- decision_sum += relu(d) ----
        for (int i = t; i < 4096; i += NTH) {
            float v = sm[S_HS + i];
            sm[S_DS + i] += v > 0.f ? v : 0.f;
        }
        __syncthreads();
    }

    // ---- final: out = ds @ out_W + out_b ----
    if (t < 64) {
        float sacc = 0.f;
#pragma unroll
        for (int j = 0; j < 64; j++)
            sacc = fmaf(sm[S_DS + SWZ(j, t)], out_W[j], sacc);
        out[tile * 64 + t] = sacc + out_b[0];
    }
}

extern "C" void kernel_launch(void* const* d_in, const int* in_sizes, int n_in,
                              void* d_out, int out_size)
{
    const float* x_num   = (const float*)d_in[0];
    const int*   x_cat   = (const int*)  d_in[1];
    const float* emb_W   = (const float*)d_in[2];
    const float* in_bn   = (const float*)d_in[3];
    const float* sh_W0   = (const float*)d_in[4];
    const float* sh_b0   = (const float*)d_in[5];
    const float* sh_bn0  = (const float*)d_in[6];
    const float* sh_W1   = (const float*)d_in[7];
    const float* sh_b1   = (const float*)d_in[8];
    const float* sh_bn1  = (const float*)d_in[9];
    const float* init_W  = (const float*)d_in[10];
    const float* init_b  = (const float*)d_in[11];
    const float* init_bn = (const float*)d_in[12];
    const float* step_W  = (const float*)d_in[13];
    const float* step_b  = (const float*)d_in[14];
    const float* step_bn = (const float*)d_in[15];
    const float* att_W   = (const float*)d_in[16];
    const float* att_b   = (const float*)d_in[17];
    const float* att_bn  = (const float*)d_in[18];
    const float* out_W   = (const float*)d_in[19];
    const float* out_b   = (const float*)d_in[20];
    float* out = (float*)d_out;

    cudaFuncSetAttribute(tabnet_kernel,
                         cudaFuncAttributeMaxDynamicSharedMemorySize, SMEM_BYTES);

    prep_kernel<<<(AC_TOTAL + 255) / 256, 256>>>(
        in_bn, sh_b0, sh_bn0, sh_b1, sh_bn1,
        init_b, init_bn, step_b, step_bn, att_b, att_bn);
    prep2_kernel<<<(62 * 8192 + 255) / 256, 256>>>(sh_W0, sh_W1, init_W, step_W);
    prep3_kernel<<<(int)(((size_t)NTILES * 20480) / NTH), NTH>>>(x_num, x_cat, emb_W);

    tabnet_kernel<<<NTILES, NTH, SMEM_BYTES>>>(att_W, out_W, out_b, out);
}

// round 15
// speedup vs baseline: 1.7239x; 1.0827x over previous
#include <cuda_runtime.h>
#include <cuda_bf16.h>
#include <stdint.h>

#define NTILES 1024
#define NTH    512
#define RES_SCALE 0.70710678118654752440f
#define GAMMA_C   1.5f

#define OFF_SH0   320
#define OFF_SH1   576
#define OFF_INIT  832
#define OFF_STEP  1344
#define OFF_ATT   3904
#define AC_TOTAL  4304

__device__ float g_A[AC_TOTAL];
__device__ float g_C[AC_TOTAL];
// W scratch: 62 chunks (32-k) x [hi: 256n x 32k][lo: 256n x 32k] bf16, n-major
__device__ __nv_bfloat16 w_scr[62 * 16384];
// x scratch: [tile][f 0..319][row 0..63] fp32, BN-folded
__device__ float xg[(size_t)NTILES * 20480];

#define SWZ(col, r) ((col) * 64 + ((r) ^ ((col) & 0x1C)))

// smem float offsets
#define S_A    0        // A hi [64r x 32k] bf16 padded 80B rows (5120B) + lo (5120B)
#define S_W    2560     // 2 bufs x (hi 20480B + lo 20480B); reused for attW+logits
#define S_XST  23040    // 2 x 2048 floats x stage
#define S_HS   27136    // hs [128 col][64 r] fp32, SWZ
#define S_MG   35328    // mask [80][64]
#define S_PR   40448    // prior [64][80]
#define S_DS   45568    // decision sum [64][64]
#define S_TOT  49664
#define SMEM_BYTES (S_TOT * 4)

__device__ __forceinline__ uint32_t smem_u32(const void* p) {
    uint32_t a;
    asm("{ .reg .u64 t; cvta.to.shared.u64 t, %1; cvt.u32.u64 %0, t; }"
        : "=r"(a) : "l"(p));
    return a;
}
__device__ __forceinline__ void cp16(unsigned dst, const void* src) {
    asm volatile("cp.async.ca.shared.global [%0], [%1], 16;" :: "r"(dst), "l"(src));
}
#define CP_COMMIT() asm volatile("cp.async.commit_group;" ::: "memory")
#define CP_WAIT0()  asm volatile("cp.async.wait_group 0;" ::: "memory")
#define CP_WAIT1()  asm volatile("cp.async.wait_group 1;" ::: "memory")

__device__ __forceinline__ void ldm_x4(uint32_t* r, uint32_t addr) {
    asm volatile("ldmatrix.sync.aligned.m8n8.x4.shared.b16 {%0,%1,%2,%3}, [%4];"
        : "=r"(r[0]), "=r"(r[1]), "=r"(r[2]), "=r"(r[3]) : "r"(addr));
}
__device__ __forceinline__ void mma_bf16(float* c, const uint32_t* a,
                                         uint32_t b0, uint32_t b1) {
    asm volatile(
        "mma.sync.aligned.m16n8k16.row.col.f32.bf16.bf16.f32 "
        "{%0,%1,%2,%3}, {%4,%5,%6,%7}, {%8,%9}, {%0,%1,%2,%3};"
        : "+f"(c[0]), "+f"(c[1]), "+f"(c[2]), "+f"(c[3])
        : "r"(a[0]), "r"(a[1]), "r"(a[2]), "r"(a[3]), "r"(b0), "r"(b1));
}

// ---------------- prep kernels ----------------
__global__ void prep_kernel(
    const float* __restrict__ in_bn,
    const float* __restrict__ sh_b0, const float* __restrict__ sh_bn0,
    const float* __restrict__ sh_b1, const float* __restrict__ sh_bn1,
    const float* __restrict__ init_b, const float* __restrict__ init_bn,
    const float* __restrict__ step_b, const float* __restrict__ step_bn,
    const float* __restrict__ att_b,  const float* __restrict__ att_bn)
{
    int idx = blockIdx.x * blockDim.x + threadIdx.x;
    if (idx >= AC_TOTAL) return;
    float s, bb, m, v, bias;
    if (idx < OFF_SH0) {
        int c = idx;
        s = in_bn[c]; bb = in_bn[320 + c]; m = in_bn[640 + c]; v = in_bn[960 + c];
        bias = 0.f;
    } else if (idx < OFF_SH1) {
        int c = idx - OFF_SH0;
        s = sh_bn0[c]; bb = sh_bn0[256 + c]; m = sh_bn0[512 + c]; v = sh_bn0[768 + c];
        bias = sh_b0[c];
    } else if (idx < OFF_INIT) {
        int c = idx - OFF_SH1;
        s = sh_bn1[c]; bb = sh_bn1[256 + c]; m = sh_bn1[512 + c]; v = sh_bn1[768 + c];
        bias = sh_b1[c];
    } else if (idx < OFF_STEP) {
        int q = (idx - OFF_INIT) >> 8, c = (idx - OFF_INIT) & 255;
        const float* p = init_bn + q * 1024;
        s = p[c]; bb = p[256 + c]; m = p[512 + c]; v = p[768 + c];
        bias = init_b[q * 256 + c];
    } else if (idx < OFF_ATT) {
        int q = (idx - OFF_STEP) >> 8, c = (idx - OFF_STEP) & 255;
        const float* p = step_bn + q * 1024;
        s = p[c]; bb = p[256 + c]; m = p[512 + c]; v = p[768 + c];
        bias = step_b[q * 256 + c];
    } else {
        int q = (idx - OFF_ATT) / 80, c = (idx - OFF_ATT) % 80;
        const float* p = att_bn + q * 320;
        s = p[c]; bb = p[80 + c]; m = p[160 + c]; v = p[240 + c];
        bias = att_b[q * 80 + c];
    }
    float A = s * rsqrtf(v + 1e-5f);
    g_A[idx] = A;
    g_C[idx] = (bias - m) * A + bb;
}

// transpose + hi/lo split weights into w_scr ([n][k] row-major per 32-k chunk)
__global__ void prep2_kernel(const float* __restrict__ sh_W0,
                             const float* __restrict__ sh_W1,
                             const float* __restrict__ init_W,
                             const float* __restrict__ step_W)
{
    int idx = blockIdx.x * blockDim.x + threadIdx.x;
    if (idx >= 62 * 8192) return;
    int c = idx >> 13, rem = idx & 8191;
    int n = rem >> 5, kin = rem & 31;
    const float* src; int kb;
    if (c < 10)      { src = sh_W0;            kb = c * 32; }
    else if (c < 14) { src = sh_W1;            kb = (c - 10) * 32; }
    else if (c < 18) { src = init_W;           kb = (c - 14) * 32; }
    else if (c < 22) { src = init_W + 128*256; kb = (c - 18) * 32; }
    else { int q = (c - 22) >> 2; src = step_W + q * 128 * 256;
           kb = ((c - 22) & 3) * 32; }
    float w = src[(kb + kin) * 256 + n];
    __nv_bfloat16 hi = __float2bfloat16(w);
    __nv_bfloat16 lo = __float2bfloat16(w - __bfloat162float(hi));
    w_scr[c * 16384 + n * 32 + kin]        = hi;
    w_scr[c * 16384 + 8192 + n * 32 + kin] = lo;
}

// BN-folded x, transposed: xg[tile][f][r]
__global__ void prep3_kernel(const float* __restrict__ x_num,
                             const int* __restrict__ x_cat,
                             const float* __restrict__ emb_W)
{
    long long idx = (long long)blockIdx.x * 256 + threadIdx.x;
    if (idx >= (long long)NTILES * 20480) return;
    int r = (int)(idx & 63);
    int f = (int)((idx >> 6) % 320);
    int tile = (int)(idx / 20480);
    int row = tile * 64 + r;
    float v;
    if (f < 64) v = x_num[row * 64 + f];
    else {
        int c = (f - 64) >> 4, j = (f - 64) & 15;
        v = emb_W[(c * 1000 + x_cat[row * 16 + c]) * 16 + j];
    }
    xg[idx] = v * g_A[f] + g_C[f];
}

// ---------------- staging helper (512 threads) ----------------
template<int MODE>
__device__ __forceinline__ void stage(int sub, int wc0, int tile,
                                      uint32_t smb, int t)
{
    int b = sub & 1;
    const __nv_bfloat16* wsrc = w_scr + (size_t)(wc0 + sub) * 16384;
    uint32_t wdst = smb + S_W * 4 + b * 40960;
#pragma unroll
    for (int i = 0; i < 4; i++) {
        int idx = t + i * 512;          // 0..2047 16B units
        int m = idx >> 10;              // 0 hi, 1 lo
        int rem = idx & 1023;
        int n = rem >> 2, k4 = rem & 3;
        cp16(wdst + m * 20480 + n * 80 + k4 * 16,
             wsrc + m * 8192 + n * 32 + k4 * 8);
    }
    if (MODE == 0) {
        const float* xsrc = xg + (size_t)tile * 20480 + sub * 2048;
        uint32_t xdst = smb + S_XST * 4 + b * 8192;
        cp16(xdst + t * 16, xsrc + t * 4);
    }
    CP_COMMIT();
}

// ---------------- fused GLU layer via mma.sync ----------------
// 16 warps = 4 row-groups x 4 col-groups; warp: 16 rows x (32 o + 32 g cols).
// MODE 0: A = mask * xg chunk; MODE 1: A = hs
template<int MODE, bool RESID>
__device__ void glu_mma(int nsub, int wc0, int acoff, int tile,
                        float* sm, uint32_t smb, int t)
{
    const int lane = t & 31, w = t >> 5;
    const int r0 = (w & 3) << 4;            // warp row base (of 64)
    const int cbase = (w >> 2) << 5;        // warp o-col base: 0,32,64,96
    const float* mg = sm + S_MG;
    const float* hs = sm + S_HS;

    float accO[4][4], accG[4][4];
#pragma unroll
    for (int j = 0; j < 4; j++)
#pragma unroll
        for (int e = 0; e < 4; e++) { accO[j][e] = 0.f; accG[j][e] = 0.f; }

    // lane-dependent ldmatrix address components (bytes)
    const uint32_t a_l = (uint32_t)(r0 + (lane & 7) + ((lane >> 3) & 1) * 8) * 80
                       + ((lane >> 4) * 8) * 2;
    const uint32_t b_l = (uint32_t)((lane & 7) + ((lane >> 4) & 1) * 8) * 80
                       + (((lane >> 3) & 1) * 8) * 2;

    stage<MODE>(0, wc0, tile, smb, t);
    stage<MODE>(1, wc0, tile, smb, t);

    for (int sub = 0; sub < nsub; sub++) {
        if (sub + 2 <= nsub) CP_WAIT1(); else CP_WAIT0();
        __syncthreads();

        // ---- convert A sub-tile to bf16 hi/lo (64r x 32k), padded 80B rows ----
        {
            const float* xst = sm + S_XST + (sub & 1) * 2048;
#pragma unroll
            for (int i = 0; i < 2; i++) {
                int el = t + i * 512;       // 1024 (r, kpair)
                int r = el & 63, kp = el >> 6, k = kp * 2;
                float x0, x1;
                if (MODE == 0) {
                    int kg = sub * 32 + k;
                    int g0 = kg < 64 ? kg : 64 + ((kg - 64) >> 4);
                    int g1 = (kg + 1) < 64 ? kg + 1 : 64 + ((kg - 63) >> 4);
                    x0 = xst[k * 64 + r] * mg[SWZ(g0, r)];
                    x1 = xst[(k + 1) * 64 + r] * mg[SWZ(g1, r)];
                } else {
                    x0 = hs[SWZ(sub * 32 + k, r)];
                    x1 = hs[SWZ(sub * 32 + k + 1, r)];
                }
                __nv_bfloat16 h0 = __float2bfloat16(x0);
                __nv_bfloat16 h1 = __float2bfloat16(x1);
                __nv_bfloat16 l0 = __float2bfloat16(x0 - __bfloat162float(h0));
                __nv_bfloat16 l1 = __float2bfloat16(x1 - __bfloat162float(h1));
                __nv_bfloat162 hp; hp.x = h0; hp.y = h1;
                __nv_bfloat162 lp; lp.x = l0; lp.y = l1;
                int off = r * 80 + k * 2;
                *(__nv_bfloat162*)((char*)sm + off) = hp;
                *(__nv_bfloat162*)((char*)sm + 5120 + off) = lp;
            }
        }
        __syncthreads();

        // ---- mma over 2 k16 steps ----
        const uint32_t wb = smb + S_W * 4 + (sub & 1) * 40960;
#pragma unroll
        for (int k16 = 0; k16 < 2; k16++) {
            uint32_t ah[4], al[4];
            ldm_x4(ah, smb + a_l + k16 * 32);
            ldm_x4(al, smb + 5120 + a_l + k16 * 32);
#pragma unroll
            for (int jp = 0; jp < 2; jp++) {
                uint32_t bh[4], bl[4];
                uint32_t nb = (uint32_t)(cbase + jp * 16) * 80 + b_l + k16 * 32;
                ldm_x4(bh, wb + nb);
                ldm_x4(bl, wb + 20480 + nb);
                mma_bf16(accO[2*jp],   ah, bh[0], bh[1]);
                mma_bf16(accO[2*jp+1], ah, bh[2], bh[3]);
                mma_bf16(accO[2*jp],   al, bh[0], bh[1]);
                mma_bf16(accO[2*jp+1], al, bh[2], bh[3]);
                mma_bf16(accO[2*jp],   ah, bl[0], bl[1]);
                mma_bf16(accO[2*jp+1], ah, bl[2], bl[3]);
            }
#pragma unroll
            for (int jp = 0; jp < 2; jp++) {
                uint32_t bh[4], bl[4];
                uint32_t nb = (uint32_t)(cbase + 128 + jp * 16) * 80 + b_l + k16 * 32;
                ldm_x4(bh, wb + nb);
                ldm_x4(bl, wb + 20480 + nb);
                mma_bf16(accG[2*jp],   ah, bh[0], bh[1]);
                mma_bf16(accG[2*jp+1], ah, bh[2], bh[3]);
                mma_bf16(accG[2*jp],   al, bh[0], bh[1]);
                mma_bf16(accG[2*jp+1], al, bh[2], bh[3]);
                mma_bf16(accG[2*jp],   ah, bl[0], bl[1]);
                mma_bf16(accG[2*jp+1], ah, bl[2], bl[3]);
            }
        }
        __syncthreads();
        if (sub + 2 < nsub) stage<MODE>(sub + 2, wc0, tile, smb, t);
    }

    // ---- epilogue: BN + GLU + residual, write hs ----
#pragma unroll
    for (int j = 0; j < 4; j++) {
        int colb = cbase + j * 8 + (lane & 3) * 2;
#pragma unroll
        for (int e = 0; e < 4; e++) {
            int row = r0 + (lane >> 2) + (e >> 1) * 8;
            int col = colb + (e & 1);
            float o = fmaf(accO[j][e], g_A[acoff + col], g_C[acoff + col]);
            float g = fmaf(accG[j][e], g_A[acoff + 128 + col],
                           g_C[acoff + 128 + col]);
            float y = o / (1.f + __expf(-g));
            float* hp = sm + S_HS + SWZ(col, row);
            if (RESID) y = (*hp + y) * RES_SCALE;
            *hp = y;
        }
    }
    __syncthreads();
}

// ---------------- main kernel ----------------
__global__ void __launch_bounds__(NTH, 1) tabnet_kernel(
    const float* __restrict__ att_W, const float* __restrict__ out_W,
    const float* __restrict__ out_b, float* __restrict__ out)
{
    extern __shared__ float sm[];
    const int t = threadIdx.x;
    const int tile = blockIdx.x;
    const uint32_t smb = smem_u32(sm);

    for (int i = t; i < 5120; i += NTH) sm[S_MG + i] = 1.f;
    for (int i = t; i < 5120; i += NTH) sm[S_PR + i] = 1.f;
    for (int i = t; i < 4096; i += NTH) sm[S_DS + i] = 0.f;
    __syncthreads();

    // ---- init pass ----
    glu_mma<0, false>(10, 0,  OFF_SH0,        tile, sm, smb, t);
    glu_mma<1, true >(4,  10, OFF_SH1,        tile, sm, smb, t);
    glu_mma<1, true >(4,  14, OFF_INIT,       tile, sm, smb, t);
    glu_mma<1, true >(4,  18, OFF_INIT + 256, tile, sm, smb, t);

    for (int s = 0; s < 5; s++) {
        // ---- attention: logits = BN(a @ att_W[s]) * prior ----
        float* wsW = sm + S_W;
        float* lg  = sm + S_W + 5120;
        float* pr  = sm + S_PR;
        float* mg  = sm + S_MG;
        const float* hs = sm + S_HS;
        const float* aw = att_W + s * 5120;
        for (int i = t; i < 5120; i += NTH) wsW[i] = aw[i];
        __syncthreads();

        if (t < 256) {
            float acc[4][5];
            const int ra = (t >> 4) << 2;
            const int c5 = (t & 15) * 5;
#pragma unroll
            for (int rr = 0; rr < 4; rr++)
#pragma unroll
                for (int j = 0; j < 5; j++) acc[rr][j] = 0.f;
#pragma unroll 4
            for (int kk = 0; kk < 64; kk++) {
                int col = 64 + kk;
                float4 av = *(const float4*)(hs + col * 64 + (ra ^ (col & 0x1C)));
                float arr[4] = {av.x, av.y, av.z, av.w};
#pragma unroll
                for (int j = 0; j < 5; j++) {
                    float wv = wsW[kk * 80 + c5 + j];
#pragma unroll
                    for (int rr = 0; rr < 4; rr++)
                        acc[rr][j] = fmaf(arr[rr], wv, acc[rr][j]);
                }
            }
            __syncthreads();
#pragma unroll
            for (int j = 0; j < 5; j++) {
                int g = c5 + j;
                float A = g_A[OFF_ATT + s * 80 + g], C = g_C[OFF_ATT + s * 80 + g];
#pragma unroll
                for (int rr = 0; rr < 4; rr++) {
                    int r = ra + rr;
                    lg[r * 80 + g] = fmaf(acc[rr][j], A, C) * pr[r * 80 + g];
                }
            }
        } else {
            __syncthreads();
        }
        __syncthreads();

        // ---- sparsemax (Michelot) ----
        if (t < 64) {
            const float* z = lg + t * 80;
            float S = 0.f;
            for (int i = 0; i < 80; i++) S += z[i];
            int k = 80;
            float tau = (S - 1.f) / 80.f;
            for (int it = 0; it < 80; it++) {
                float S2 = 0.f; int k2 = 0;
                for (int i = 0; i < 80; i++) {
                    float zi = z[i];
                    if (zi > tau) { S2 += zi; k2++; }
                }
                if (k2 == k) break;
                k = k2;
                tau = (S2 - 1.f) / (float)k2;
            }
            for (int g = 0; g < 80; g++) {
                float m_ = z[g] - tau;
                m_ = m_ > 0.f ? m_ : 0.f;
                mg[SWZ(g, t)] = m_;
                pr[t * 80 + g] *= (GAMMA_C - m_);
            }
        }
        __syncthreads();

        // ---- masked ft pass ----
        glu_mma<0, false>(10, 0,      OFF_SH0,                  tile, sm, smb, t);
        glu_mma<1, true >(4,  10,     OFF_SH1,                  tile, sm, smb, t);
        glu_mma<1, true >(4,  22+8*s, OFF_STEP + (2*s) * 256,   tile, sm, smb, t);
        glu_mma<1, true >(4,  26+8*s, OFF_STEP + (2*s+1) * 256, tile, sm, smb, t);

        // ---- decision_sum += relu(d) ----
        for (int i = t; i < 4096; i += NTH) {
            float v = sm[S_HS + i];
            sm[S_DS + i] += v > 0.f ? v : 0.f;
        }
        __syncthreads();
    }

    // ---- final: out = ds @ out_W + out_b ----
    if (t < 64) {
        float sacc = 0.f;
#pragma unroll
        for (int j = 0; j < 64; j++)
            sacc = fmaf(sm[S_DS + SWZ(j, t)], out_W[j], sacc);
        out[tile * 64 + t] = sacc + out_b[0];
    }
}

extern "C" void kernel_launch(void* const* d_in, const int* in_sizes, int n_in,
                              void* d_out, int out_size)
{
    const float* x_num   = (const float*)d_in[0];
    const int*   x_cat   = (const int*)  d_in[1];
    const float* emb_W   = (const float*)d_in[2];
    const float* in_bn   = (const float*)d_in[3];
    const float* sh_W0   = (const float*)d_in[4];
    const float* sh_b0   = (const float*)d_in[5];
    const float* sh_bn0  = (const float*)d_in[6];
    const float* sh_W1   = (const float*)d_in[7];
    const float* sh_b1   = (const float*)d_in[8];
    const float* sh_bn1  = (const float*)d_in[9];
    const float* init_W  = (const float*)d_in[10];
    const float* init_b  = (const float*)d_in[11];
    const float* init_bn = (const float*)d_in[12];
    const float* step_W  = (const float*)d_in[13];
    const float* step_b  = (const float*)d_in[14];
    const float* step_bn = (const float*)d_in[15];
    const float* att_W   = (const float*)d_in[16];
    const float* att_b   = (const float*)d_in[17];
    const float* att_bn  = (const float*)d_in[18];
    const float* out_W   = (const float*)d_in[19];
    const float* out_b   = (const float*)d_in[20];
    float* out = (float*)d_out;

    cudaFuncSetAttribute(tabnet_kernel,
                         cudaFuncAttributeMaxDynamicSharedMemorySize, SMEM_BYTES);

    prep_kernel<<<(AC_TOTAL + 255) / 256, 256>>>(
        in_bn, sh_b0, sh_bn0, sh_b1, sh_bn1,
        init_b, init_bn, step_b, step_bn, att_b, att_bn);
    prep2_kernel<<<(62 * 8192 + 255) / 256, 256>>>(sh_W0, sh_W1, init_W, step_W);
    prep3_kernel<<<(int)(((size_t)NTILES * 20480) / 256), 256>>>(x_num, x_cat, emb_W);

    tabnet_kernel<<<NTILES, NTH, SMEM_BYTES>>>(att_W, out_W, out_b, out);
}

// round 16
// speedup vs baseline: 2.4532x; 1.4231x over previous
#include <cuda_runtime.h>
#include <cuda_fp16.h>
#include <stdint.h>

#define NTILES 1024
#define NTH    512
#define RES_SCALE 0.70710678118654752440f
#define GAMMA_C   1.5f

#define OFF_SH0   320
#define OFF_SH1   576
#define OFF_INIT  832
#define OFF_STEP  1344
#define OFF_ATT   3904
#define AC_TOTAL  4304

__device__ float g_A[AC_TOTAL];
__device__ float g_C[AC_TOTAL];
// W scratch: 62 chunks (32-k) x [256 n x 32 k] fp16, n-major
__device__ __half w_scr[62 * 8192];
// x scratch: [tile][f 0..319][row 0..63] fp32, BN-folded
__device__ float xg[(size_t)NTILES * 20480];

#define SWZ(col, r) ((col) * 64 + ((r) ^ ((col) & 0x1C)))

// smem float offsets
#define S_A    0        // A fp16 [64r x 32k] padded 80B rows = 5120B
#define S_W    1280     // 2 bufs x 20480B (256n x 80B); reused for attW+logits
#define S_XST  11520    // 2 x 2048 floats x stage
#define S_HS   15616    // hs [128 col][64 r] fp32, SWZ
#define S_MG   23808    // mask [80][64]
#define S_PR   28928    // prior [64][80]
#define S_DS   34048    // decision sum [64][64]
#define S_TOT  38144
#define SMEM_BYTES (S_TOT * 4)

__device__ __forceinline__ uint32_t smem_u32(const void* p) {
    uint32_t a;
    asm("{ .reg .u64 t; cvta.to.shared.u64 t, %1; cvt.u32.u64 %0, t; }"
        : "=r"(a) : "l"(p));
    return a;
}
__device__ __forceinline__ void cp16(unsigned dst, const void* src) {
    asm volatile("cp.async.ca.shared.global [%0], [%1], 16;" :: "r"(dst), "l"(src));
}
#define CP_COMMIT() asm volatile("cp.async.commit_group;" ::: "memory")
#define CP_WAIT0()  asm volatile("cp.async.wait_group 0;" ::: "memory")
#define CP_WAIT1()  asm volatile("cp.async.wait_group 1;" ::: "memory")

__device__ __forceinline__ void ldm_x4(uint32_t* r, uint32_t addr) {
    asm volatile("ldmatrix.sync.aligned.m8n8.x4.shared.b16 {%0,%1,%2,%3}, [%4];"
        : "=r"(r[0]), "=r"(r[1]), "=r"(r[2]), "=r"(r[3]) : "r"(addr));
}
__device__ __forceinline__ void mma_f16(float* c, const uint32_t* a,
                                        uint32_t b0, uint32_t b1) {
    asm volatile(
        "mma.sync.aligned.m16n8k16.row.col.f32.f16.f16.f32 "
        "{%0,%1,%2,%3}, {%4,%5,%6,%7}, {%8,%9}, {%0,%1,%2,%3};"
        : "+f"(c[0]), "+f"(c[1]), "+f"(c[2]), "+f"(c[3])
        : "r"(a[0]), "r"(a[1]), "r"(a[2]), "r"(a[3]), "r"(b0), "r"(b1));
}

// ---------------- prep kernels ----------------
__global__ void prep_kernel(
    const float* __restrict__ in_bn,
    const float* __restrict__ sh_b0, const float* __restrict__ sh_bn0,
    const float* __restrict__ sh_b1, const float* __restrict__ sh_bn1,
    const float* __restrict__ init_b, const float* __restrict__ init_bn,
    const float* __restrict__ step_b, const float* __restrict__ step_bn,
    const float* __restrict__ att_b,  const float* __restrict__ att_bn)
{
    int idx = blockIdx.x * blockDim.x + threadIdx.x;
    if (idx >= AC_TOTAL) return;
    float s, bb, m, v, bias;
    if (idx < OFF_SH0) {
        int c = idx;
        s = in_bn[c]; bb = in_bn[320 + c]; m = in_bn[640 + c]; v = in_bn[960 + c];
        bias = 0.f;
    } else if (idx < OFF_SH1) {
        int c = idx - OFF_SH0;
        s = sh_bn0[c]; bb = sh_bn0[256 + c]; m = sh_bn0[512 + c]; v = sh_bn0[768 + c];
        bias = sh_b0[c];
    } else if (idx < OFF_INIT) {
        int c = idx - OFF_SH1;
        s = sh_bn1[c]; bb = sh_bn1[256 + c]; m = sh_bn1[512 + c]; v = sh_bn1[768 + c];
        bias = sh_b1[c];
    } else if (idx < OFF_STEP) {
        int q = (idx - OFF_INIT) >> 8, c = (idx - OFF_INIT) & 255;
        const float* p = init_bn + q * 1024;
        s = p[c]; bb = p[256 + c]; m = p[512 + c]; v = p[768 + c];
        bias = init_b[q * 256 + c];
    } else if (idx < OFF_ATT) {
        int q = (idx - OFF_STEP) >> 8, c = (idx - OFF_STEP) & 255;
        const float* p = step_bn + q * 1024;
        s = p[c]; bb = p[256 + c]; m = p[512 + c]; v = p[768 + c];
        bias = step_b[q * 256 + c];
    } else {
        int q = (idx - OFF_ATT) / 80, c = (idx - OFF_ATT) % 80;
        const float* p = att_bn + q * 320;
        s = p[c]; bb = p[80 + c]; m = p[160 + c]; v = p[240 + c];
        bias = att_b[q * 80 + c];
    }
    float A = s * rsqrtf(v + 1e-5f);
    g_A[idx] = A;
    g_C[idx] = (bias - m) * A + bb;
}

// transpose weights into w_scr fp16 ([n][k] row-major per 32-k chunk)
__global__ void prep2_kernel(const float* __restrict__ sh_W0,
                             const float* __restrict__ sh_W1,
                             const float* __restrict__ init_W,
                             const float* __restrict__ step_W)
{
    int idx = blockIdx.x * blockDim.x + threadIdx.x;
    if (idx >= 62 * 8192) return;
    int c = idx >> 13, rem = idx & 8191;
    int n = rem >> 5, kin = rem & 31;
    const float* src; int kb;
    if (c < 10)      { src = sh_W0;            kb = c * 32; }
    else if (c < 14) { src = sh_W1;            kb = (c - 10) * 32; }
    else if (c < 18) { src = init_W;           kb = (c - 14) * 32; }
    else if (c < 22) { src = init_W + 128*256; kb = (c - 18) * 32; }
    else { int q = (c - 22) >> 2; src = step_W + q * 128 * 256;
           kb = ((c - 22) & 3) * 32; }
    w_scr[c * 8192 + n * 32 + kin] = __float2half(src[(kb + kin) * 256 + n]);
}

// BN-folded x, transposed: xg[tile][f][r]
__global__ void prep3_kernel(const float* __restrict__ x_num,
                             const int* __restrict__ x_cat,
                             const float* __restrict__ emb_W)
{
    long long idx = (long long)blockIdx.x * 256 + threadIdx.x;
    if (idx >= (long long)NTILES * 20480) return;
    int r = (int)(idx & 63);
    int f = (int)((idx >> 6) % 320);
    int tile = (int)(idx / 20480);
    int row = tile * 64 + r;
    float v;
    if (f < 64) v = x_num[row * 64 + f];
    else {
        int c = (f - 64) >> 4, j = (f - 64) & 15;
        v = emb_W[(c * 1000 + x_cat[row * 16 + c]) * 16 + j];
    }
    xg[idx] = v * g_A[f] + g_C[f];
}

// ---------------- staging helper (512 threads) ----------------
template<int MODE>
__device__ __forceinline__ void stage(int sub, int wc0, int tile,
                                      uint32_t smb, int t)
{
    int b = sub & 1;
    const __half* wsrc = w_scr + (size_t)(wc0 + sub) * 8192;
    uint32_t wdst = smb + S_W * 4 + b * 20480;
#pragma unroll
    for (int i = 0; i < 2; i++) {
        int idx = t + i * 512;          // 0..1023 16B units
        int n = idx >> 2, k4 = idx & 3;
        cp16(wdst + n * 80 + k4 * 16, wsrc + n * 32 + k4 * 8);
    }
    if (MODE == 0) {
        const float* xsrc = xg + (size_t)tile * 20480 + sub * 2048;
        uint32_t xdst = smb + S_XST * 4 + b * 8192;
        cp16(xdst + t * 16, xsrc + t * 4);
    }
    CP_COMMIT();
}

// ---------------- fused GLU layer via fp16 mma.sync ----------------
// 16 warps = 4 row-groups x 4 col-groups; warp: 16 rows x (32 o + 32 g cols).
// MODE 0: A = mask * xg chunk; MODE 1: A = hs
template<int MODE, bool RESID>
__device__ void glu_mma(int nsub, int wc0, int acoff, int tile,
                        float* sm, uint32_t smb, int t)
{
    const int lane = t & 31, w = t >> 5;
    const int r0 = (w & 3) << 4;            // warp row base (of 64)
    const int cbase = (w >> 2) << 5;        // warp o-col base: 0,32,64,96
    const float* mg = sm + S_MG;
    const float* hs = sm + S_HS;

    float accO[4][4], accG[4][4];
#pragma unroll
    for (int j = 0; j < 4; j++)
#pragma unroll
        for (int e = 0; e < 4; e++) { accO[j][e] = 0.f; accG[j][e] = 0.f; }

    // lane-dependent ldmatrix address components (bytes)
    const uint32_t a_l = (uint32_t)(r0 + (lane & 7) + ((lane >> 3) & 1) * 8) * 80
                       + ((lane >> 4) * 8) * 2;
    const uint32_t b_l = (uint32_t)((lane & 7) + ((lane >> 4) & 1) * 8) * 80
                       + (((lane >> 3) & 1) * 8) * 2;

    stage<MODE>(0, wc0, tile, smb, t);
    stage<MODE>(1, wc0, tile, smb, t);

    for (int sub = 0; sub < nsub; sub++) {
        if (sub + 2 <= nsub) CP_WAIT1(); else CP_WAIT0();
        __syncthreads();

        // ---- convert A sub-tile to fp16 (64r x 32k), padded 80B rows ----
        {
            const float* xst = sm + S_XST + (sub & 1) * 2048;
#pragma unroll
            for (int i = 0; i < 2; i++) {
                int el = t + i * 512;       // 1024 (r, kpair)
                int r = el & 63, kp = el >> 6, k = kp * 2;
                float x0, x1;
                if (MODE == 0) {
                    int kg = sub * 32 + k;
                    int g0 = kg < 64 ? kg : 64 + ((kg - 64) >> 4);
                    int g1 = (kg + 1) < 64 ? kg + 1 : 64 + ((kg - 63) >> 4);
                    x0 = xst[k * 64 + r] * mg[SWZ(g0, r)];
                    x1 = xst[(k + 1) * 64 + r] * mg[SWZ(g1, r)];
                } else {
                    x0 = hs[SWZ(sub * 32 + k, r)];
                    x1 = hs[SWZ(sub * 32 + k + 1, r)];
                }
                __half2 hp;
                hp.x = __float2half(x0);
                hp.y = __float2half(x1);
                *(__half2*)((char*)sm + r * 80 + k * 2) = hp;
            }
        }
        __syncthreads();

        // ---- mma over 2 k16 steps ----
        const uint32_t wb = smb + S_W * 4 + (sub & 1) * 20480;
#pragma unroll
        for (int k16 = 0; k16 < 2; k16++) {
            uint32_t ah[4];
            ldm_x4(ah, smb + a_l + k16 * 32);
#pragma unroll
            for (int jp = 0; jp < 2; jp++) {
                uint32_t bh[4];
                uint32_t nb = (uint32_t)(cbase + jp * 16) * 80 + b_l + k16 * 32;
                ldm_x4(bh, wb + nb);
                mma_f16(accO[2*jp],   ah, bh[0], bh[1]);
                mma_f16(accO[2*jp+1], ah, bh[2], bh[3]);
            }
#pragma unroll
            for (int jp = 0; jp < 2; jp++) {
                uint32_t bh[4];
                uint32_t nb = (uint32_t)(cbase + 128 + jp * 16) * 80 + b_l + k16 * 32;
                ldm_x4(bh, wb + nb);
                mma_f16(accG[2*jp],   ah, bh[0], bh[1]);
                mma_f16(accG[2*jp+1], ah, bh[2], bh[3]);
            }
        }
        __syncthreads();
        if (sub + 2 < nsub) stage<MODE>(sub + 2, wc0, tile, smb, t);
    }

    // ---- epilogue: BN + GLU + residual, write hs ----
#pragma unroll
    for (int j = 0; j < 4; j++) {
        int colb = cbase + j * 8 + (lane & 3) * 2;
#pragma unroll
        for (int e = 0; e < 4; e++) {
            int row = r0 + (lane >> 2) + (e >> 1) * 8;
            int col = colb + (e & 1);
            float o = fmaf(accO[j][e], g_A[acoff + col], g_C[acoff + col]);
            float g = fmaf(accG[j][e], g_A[acoff + 128 + col],
                           g_C[acoff + 128 + col]);
            float y = o / (1.f + __expf(-g));
            float* hp = sm + S_HS + SWZ(col, row);
            if (RESID) y = (*hp + y) * RES_SCALE;
            *hp = y;
        }
    }
    __syncthreads();
}

// ---------------- main kernel ----------------
__global__ void __launch_bounds__(NTH, 1) tabnet_kernel(
    const float* __restrict__ att_W, const float* __restrict__ out_W,
    const float* __restrict__ out_b, float* __restrict__ out)
{
    extern __shared__ float sm[];
    const int t = threadIdx.x;
    const int tile = blockIdx.x;
    const uint32_t smb = smem_u32(sm);

    for (int i = t; i < 5120; i += NTH) sm[S_MG + i] = 1.f;
    for (int i = t; i < 5120; i += NTH) sm[S_PR + i] = 1.f;
    for (int i = t; i < 4096; i += NTH) sm[S_DS + i] = 0.f;
    __syncthreads();

    // ---- init pass ----
    glu_mma<0, false>(10, 0,  OFF_SH0,        tile, sm, smb, t);
    glu_mma<1, true >(4,  10, OFF_SH1,        tile, sm, smb, t);
    glu_mma<1, true >(4,  14, OFF_INIT,       tile, sm, smb, t);
    glu_mma<1, true >(4,  18, OFF_INIT + 256, tile, sm, smb, t);

    for (int s = 0; s < 5; s++) {
        // ---- attention: logits = BN(a @ att_W[s]) * prior ----
        float* wsW = sm + S_W;
        float* lg  = sm + S_W + 5120;
        float* pr  = sm + S_PR;
        float* mg  = sm + S_MG;
        const float* hs = sm + S_HS;
        const float* aw = att_W + s * 5120;
        for (int i = t; i < 5120; i += NTH) wsW[i] = aw[i];
        __syncthreads();

        if (t < 256) {
            float acc[4][5];
            const int ra = (t >> 4) << 2;
            const int c5 = (t & 15) * 5;
#pragma unroll
            for (int rr = 0; rr < 4; rr++)
#pragma unroll
                for (int j = 0; j < 5; j++) acc[rr][j] = 0.f;
#pragma unroll 4
            for (int kk = 0; kk < 64; kk++) {
                int col = 64 + kk;
                float4 av = *(const float4*)(hs + col * 64 + (ra ^ (col & 0x1C)));
                float arr[4] = {av.x, av.y, av.z, av.w};
#pragma unroll
                for (int j = 0; j < 5; j++) {
                    float wv = wsW[kk * 80 + c5 + j];
#pragma unroll
                    for (int rr = 0; rr < 4; rr++)
                        acc[rr][j] = fmaf(arr[rr], wv, acc[rr][j]);
                }
            }
            __syncthreads();
#pragma unroll
            for (int j = 0; j < 5; j++) {
                int g = c5 + j;
                float A = g_A[OFF_ATT + s * 80 + g], C = g_C[OFF_ATT + s * 80 + g];
#pragma unroll
                for (int rr = 0; rr < 4; rr++) {
                    int r = ra + rr;
                    lg[r * 80 + g] = fmaf(acc[rr][j], A, C) * pr[r * 80 + g];
                }
            }
        } else {
            __syncthreads();
        }
        __syncthreads();

        // ---- sparsemax (Michelot) ----
        if (t < 64) {
            const float* z = lg + t * 80;
            float S = 0.f;
            for (int i = 0; i < 80; i++) S += z[i];
            int k = 80;
            float tau = (S - 1.f) / 80.f;
            for (int it = 0; it < 80; it++) {
                float S2 = 0.f; int k2 = 0;
                for (int i = 0; i < 80; i++) {
                    float zi = z[i];
                    if (zi > tau) { S2 += zi; k2++; }
                }
                if (k2 == k) break;
                k = k2;
                tau = (S2 - 1.f) / (float)k2;
            }
            for (int g = 0; g < 80; g++) {
                float m_ = z[g] - tau;
                m_ = m_ > 0.f ? m_ : 0.f;
                mg[SWZ(g, t)] = m_;
                pr[t * 80 + g] *= (GAMMA_C - m_);
            }
        }
        __syncthreads();

        // ---- masked ft pass ----
        glu_mma<0, false>(10, 0,      OFF_SH0,                  tile, sm, smb, t);
        glu_mma<1, true >(4,  10,     OFF_SH1,                  tile, sm, smb, t);
        glu_mma<1, true >(4,  22+8*s, OFF_STEP + (2*s) * 256,   tile, sm, smb, t);
        glu_mma<1, true >(4,  26+8*s, OFF_STEP + (2*s+1) * 256, tile, sm, smb, t);

        // ---- decision_sum += relu(d) ----
        for (int i = t; i < 4096; i += NTH) {
            float v = sm[S_HS + i];
            sm[S_DS + i] += v > 0.f ? v : 0.f;
        }
        __syncthreads();
    }

    // ---- final: out = ds @ out_W + out_b ----
    if (t < 64) {
        float sacc = 0.f;
#pragma unroll
        for (int j = 0; j < 64; j++)
            sacc = fmaf(sm[S_DS + SWZ(j, t)], out_W[j], sacc);
        out[tile * 64 + t] = sacc + out_b[0];
    }
}

extern "C" void kernel_launch(void* const* d_in, const int* in_sizes, int n_in,
                              void* d_out, int out_size)
{
    const float* x_num   = (const float*)d_in[0];
    const int*   x_cat   = (const int*)  d_in[1];
    const float* emb_W   = (const float*)d_in[2];
    const float* in_bn   = (const float*)d_in[3];
    const float* sh_W0   = (const float*)d_in[4];
    const float* sh_b0   = (const float*)d_in[5];
    const float* sh_bn0  = (const float*)d_in[6];
    const float* sh_W1   = (const float*)d_in[7];
    const float* sh_b1   = (const float*)d_in[8];
    const float* sh_bn1  = (const float*)d_in[9];
    const float* init_W  = (const float*)d_in[10];
    const float* init_b  = (const float*)d_in[11];
    const float* init_bn = (const float*)d_in[12];
    const float* step_W  = (const float*)d_in[13];
    const float* step_b  = (const float*)d_in[14];
    const float* step_bn = (const float*)d_in[15];
    const float* att_W   = (const float*)d_in[16];
    const float* att_b   = (const float*)d_in[17];
    const float* att_bn  = (const float*)d_in[18];
    const float* out_W   = (const float*)d_in[19];
    const float* out_b   = (const float*)d_in[20];
    float* out = (float*)d_out;

    cudaFuncSetAttribute(tabnet_kernel,
                         cudaFuncAttributeMaxDynamicSharedMemorySize, SMEM_BYTES);

    prep_kernel<<<(AC_TOTAL + 255) / 256, 256>>>(
        in_bn, sh_b0, sh_bn0, sh_b1, sh_bn1,
        init_b, init_bn, step_b, step_bn, att_b, att_bn);
    prep2_kernel<<<(62 * 8192 + 255) / 256, 256>>>(sh_W0, sh_W1, init_W, step_W);
    prep3_kernel<<<(int)(((size_t)NTILES * 20480) / 256), 256>>>(x_num, x_cat, emb_W);

    tabnet_kernel<<<NTILES, NTH, SMEM_BYTES>>>(att_W, out_W, out_b, out);
}

// round 17
// speedup vs baseline: 2.5305x; 1.0315x over previous
#include <cuda_runtime.h>
#include <cuda_fp16.h>
#include <stdint.h>

#define NTILES 1024
#define NTH    512
#define RES_SCALE 0.70710678118654752440f
#define GAMMA_C   1.5f

#define OFF_SH0   320
#define OFF_SH1   576
#define OFF_INIT  832
#define OFF_STEP  1344
#define OFF_ATT   3904
#define AC_TOTAL  4304

__device__ float g_A[AC_TOTAL];
__device__ float g_C[AC_TOTAL];
// W scratch: 62 chunks (32-k) x [256 n x 32 k] fp16, n-major
__device__ __half w_scr[62 * 8192];
// x scratch: [tile][f 0..319][row 0..63] fp32, BN-folded
__device__ float xg[(size_t)NTILES * 20480];

#define SWZ(col, r) ((col) * 64 + ((r) ^ ((col) & 0x1C)))

// smem float offsets
#define S_A    0        // A fp16 [64r x 32k] padded 80B rows = 5120B (MODE0 tile)
#define S_W    1280     // 3 bufs x 20480B; also attW(5120f)+logits during att
#define S_XST  16640    // 3 bufs x 8192B x stage
#define S_AF   22784    // fp16 A-layout activation [4 subs][64r x 32k] = 20480B
#define S_HS   27904    // hs [128 col][64 r] fp32, SWZ
#define S_MG   36096    // mask [80][64]
#define S_PR   41216    // prior [64][80]
#define S_DS   46336    // decision sum [64][64]
#define S_TOT  50432
#define SMEM_BYTES (S_TOT * 4)

__device__ __forceinline__ uint32_t smem_u32(const void* p) {
    uint32_t a;
    asm("{ .reg .u64 t; cvta.to.shared.u64 t, %1; cvt.u32.u64 %0, t; }"
        : "=r"(a) : "l"(p));
    return a;
}
__device__ __forceinline__ void cp16(unsigned dst, const void* src) {
    asm volatile("cp.async.ca.shared.global [%0], [%1], 16;" :: "r"(dst), "l"(src));
}
#define CP_COMMIT() asm volatile("cp.async.commit_group;" ::: "memory")
#define CP_WAIT0()  asm volatile("cp.async.wait_group 0;" ::: "memory")
#define CP_WAIT1()  asm volatile("cp.async.wait_group 1;" ::: "memory")

__device__ __forceinline__ void ldm_x4(uint32_t* r, uint32_t addr) {
    asm volatile("ldmatrix.sync.aligned.m8n8.x4.shared.b16 {%0,%1,%2,%3}, [%4];"
        : "=r"(r[0]), "=r"(r[1]), "=r"(r[2]), "=r"(r[3]) : "r"(addr));
}
__device__ __forceinline__ void mma_f16(float* c, const uint32_t* a,
                                        uint32_t b0, uint32_t b1) {
    asm volatile(
        "mma.sync.aligned.m16n8k16.row.col.f32.f16.f16.f32 "
        "{%0,%1,%2,%3}, {%4,%5,%6,%7}, {%8,%9}, {%0,%1,%2,%3};"
        : "+f"(c[0]), "+f"(c[1]), "+f"(c[2]), "+f"(c[3])
        : "r"(a[0]), "r"(a[1]), "r"(a[2]), "r"(a[3]), "r"(b0), "r"(b1));
}

// ---------------- prep kernels ----------------
__global__ void prep_kernel(
    const float* __restrict__ in_bn,
    const float* __restrict__ sh_b0, const float* __restrict__ sh_bn0,
    const float* __restrict__ sh_b1, const float* __restrict__ sh_bn1,
    const float* __restrict__ init_b, const float* __restrict__ init_bn,
    const float* __restrict__ step_b, const float* __restrict__ step_bn,
    const float* __restrict__ att_b,  const float* __restrict__ att_bn)
{
    int idx = blockIdx.x * blockDim.x + threadIdx.x;
    if (idx >= AC_TOTAL) return;
    float s, bb, m, v, bias;
    if (idx < OFF_SH0) {
        int c = idx;
        s = in_bn[c]; bb = in_bn[320 + c]; m = in_bn[640 + c]; v = in_bn[960 + c];
        bias = 0.f;
    } else if (idx < OFF_SH1) {
        int c = idx - OFF_SH0;
        s = sh_bn0[c]; bb = sh_bn0[256 + c]; m = sh_bn0[512 + c]; v = sh_bn0[768 + c];
        bias = sh_b0[c];
    } else if (idx < OFF_INIT) {
        int c = idx - OFF_SH1;
        s = sh_bn1[c]; bb = sh_bn1[256 + c]; m = sh_bn1[512 + c]; v = sh_bn1[768 + c];
        bias = sh_b1[c];
    } else if (idx < OFF_STEP) {
        int q = (idx - OFF_INIT) >> 8, c = (idx - OFF_INIT) & 255;
        const float* p = init_bn + q * 1024;
        s = p[c]; bb = p[256 + c]; m = p[512 + c]; v = p[768 + c];
        bias = init_b[q * 256 + c];
    } else if (idx < OFF_ATT) {
        int q = (idx - OFF_STEP) >> 8, c = (idx - OFF_STEP) & 255;
        const float* p = step_bn + q * 1024;
        s = p[c]; bb = p[256 + c]; m = p[512 + c]; v = p[768 + c];
        bias = step_b[q * 256 + c];
    } else {
        int q = (idx - OFF_ATT) / 80, c = (idx - OFF_ATT) % 80;
        const float* p = att_bn + q * 320;
        s = p[c]; bb = p[80 + c]; m = p[160 + c]; v = p[240 + c];
        bias = att_b[q * 80 + c];
    }
    float A = s * rsqrtf(v + 1e-5f);
    g_A[idx] = A;
    g_C[idx] = (bias - m) * A + bb;
}

// transpose weights into w_scr fp16 ([n][k] row-major per 32-k chunk)
__global__ void prep2_kernel(const float* __restrict__ sh_W0,
                             const float* __restrict__ sh_W1,
                             const float* __restrict__ init_W,
                             const float* __restrict__ step_W)
{
    int idx = blockIdx.x * blockDim.x + threadIdx.x;
    if (idx >= 62 * 8192) return;
    int c = idx >> 13, rem = idx & 8191;
    int n = rem >> 5, kin = rem & 31;
    const float* src; int kb;
    if (c < 10)      { src = sh_W0;            kb = c * 32; }
    else if (c < 14) { src = sh_W1;            kb = (c - 10) * 32; }
    else if (c < 18) { src = init_W;           kb = (c - 14) * 32; }
    else if (c < 22) { src = init_W + 128*256; kb = (c - 18) * 32; }
    else { int q = (c - 22) >> 2; src = step_W + q * 128 * 256;
           kb = ((c - 22) & 3) * 32; }
    w_scr[c * 8192 + n * 32 + kin] = __float2half(src[(kb + kin) * 256 + n]);
}

// BN-folded x, transposed: xg[tile][f][r]
__global__ void prep3_kernel(const float* __restrict__ x_num,
                             const int* __restrict__ x_cat,
                             const float* __restrict__ emb_W)
{
    long long idx = (long long)blockIdx.x * 256 + threadIdx.x;
    if (idx >= (long long)NTILES * 20480) return;
    int r = (int)(idx & 63);
    int f = (int)((idx >> 6) % 320);
    int tile = (int)(idx / 20480);
    int row = tile * 64 + r;
    float v;
    if (f < 64) v = x_num[row * 64 + f];
    else {
        int c = (f - 64) >> 4, j = (f - 64) & 15;
        v = emb_W[(c * 1000 + x_cat[row * 16 + c]) * 16 + j];
    }
    xg[idx] = v * g_A[f] + g_C[f];
}

// ---------------- staging helper (512 threads, 3-buffer rings) ----------------
template<int MODE>
__device__ __forceinline__ void stage(int sub, int wc0, int tile,
                                      uint32_t smb, int t)
{
    int b = sub % 3;
    const __half* wsrc = w_scr + (size_t)(wc0 + sub) * 8192;
    uint32_t wdst = smb + S_W * 4 + b * 20480;
#pragma unroll
    for (int i = 0; i < 2; i++) {
        int idx = t + i * 512;          // 0..1023 16B units
        int n = idx >> 2, k4 = idx & 3;
        cp16(wdst + n * 80 + k4 * 16, wsrc + n * 32 + k4 * 8);
    }
    if (MODE == 0) {
        const float* xsrc = xg + (size_t)tile * 20480 + sub * 2048;
        uint32_t xdst = smb + S_XST * 4 + b * 8192;
        cp16(xdst + t * 16, xsrc + t * 4);
    }
    CP_COMMIT();
}

// ---------------- fused GLU layer via fp16 mma.sync ----------------
// 16 warps = 4 row-groups x 4 col-groups; warp: 16 rows x (32 o + 32 g cols).
// MODE 0: A = mask * xg chunk (converted per sub into S_A);
// MODE 1: A = af (fp16 A-layout, written by previous layer's epilogue).
template<int MODE, bool RESID>
__device__ void glu_mma(int nsub, int wc0, int acoff, int tile,
                        float* sm, uint32_t smb, int t)
{
    const int lane = t & 31, w = t >> 5;
    const int r0 = (w & 3) << 4;            // warp row base (of 64)
    const int cbase = (w >> 2) << 5;        // warp o-col base: 0,32,64,96
    const float* mg = sm + S_MG;

    float accO[4][4], accG[4][4];
#pragma unroll
    for (int j = 0; j < 4; j++)
#pragma unroll
        for (int e = 0; e < 4; e++) { accO[j][e] = 0.f; accG[j][e] = 0.f; }

    // lane-dependent ldmatrix address components (bytes)
    const uint32_t a_l = (uint32_t)(r0 + (lane & 7) + ((lane >> 3) & 1) * 8) * 80
                       + ((lane >> 4) * 8) * 2;
    const uint32_t b_l = (uint32_t)((lane & 7) + ((lane >> 4) & 1) * 8) * 80
                       + (((lane >> 3) & 1) * 8) * 2;

    stage<MODE>(0, wc0, tile, smb, t);
    stage<MODE>(1, wc0, tile, smb, t);

    for (int sub = 0; sub < nsub; sub++) {
        if (sub + 2 <= nsub) CP_WAIT1(); else CP_WAIT0();
        __syncthreads();
        if (sub + 2 < nsub) stage<MODE>(sub + 2, wc0, tile, smb, t);

        uint32_t abase;
        if (MODE == 0) {
            // ---- convert masked x sub-tile to fp16 (64r x 32k), 80B rows ----
            const float* xst = sm + S_XST + (sub % 3) * 2048;
#pragma unroll
            for (int i = 0; i < 2; i++) {
                int el = t + i * 512;       // 1024 (r, kpair)
                int r = el & 63, kp = el >> 6, k = kp * 2;
                int kg = sub * 32 + k;
                int g0 = kg < 64 ? kg : 64 + ((kg - 64) >> 4);
                int g1 = (kg + 1) < 64 ? kg + 1 : 64 + ((kg - 63) >> 4);
                float x0 = xst[k * 64 + r] * mg[SWZ(g0, r)];
                float x1 = xst[(k + 1) * 64 + r] * mg[SWZ(g1, r)];
                __half2 hp;
                hp.x = __float2half(x0);
                hp.y = __float2half(x1);
                *(__half2*)((char*)sm + r * 80 + k * 2) = hp;
            }
            __syncthreads();
            abase = smb;                    // S_A = 0
        } else {
            abase = smb + S_AF * 4 + sub * 5120;
        }

        // ---- mma over 2 k16 steps ----
        const uint32_t wb = smb + S_W * 4 + (sub % 3) * 20480;
#pragma unroll
        for (int k16 = 0; k16 < 2; k16++) {
            uint32_t ah[4];
            ldm_x4(ah, abase + a_l + k16 * 32);
#pragma unroll
            for (int jp = 0; jp < 2; jp++) {
                uint32_t bh[4];
                uint32_t nb = (uint32_t)(cbase + jp * 16) * 80 + b_l + k16 * 32;
                ldm_x4(bh, wb + nb);
                mma_f16(accO[2*jp],   ah, bh[0], bh[1]);
                mma_f16(accO[2*jp+1], ah, bh[2], bh[3]);
            }
#pragma unroll
            for (int jp = 0; jp < 2; jp++) {
                uint32_t bh[4];
                uint32_t nb = (uint32_t)(cbase + 128 + jp * 16) * 80 + b_l + k16 * 32;
                ldm_x4(bh, wb + nb);
                mma_f16(accG[2*jp],   ah, bh[0], bh[1]);
                mma_f16(accG[2*jp+1], ah, bh[2], bh[3]);
            }
        }
    }
    __syncthreads();    // all mma done before af/hs overwrite

    // ---- epilogue: BN + GLU + residual; write hs (fp32) + af (fp16 A-layout) ----
    __half* afp = (__half*)(sm + S_AF);
#pragma unroll
    for (int j = 0; j < 4; j++) {
        int colb = cbase + j * 8 + (lane & 3) * 2;
#pragma unroll
        for (int e = 0; e < 4; e++) {
            int row = r0 + (lane >> 2) + (e >> 1) * 8;
            int col = colb + (e & 1);
            float o = fmaf(accO[j][e], g_A[acoff + col], g_C[acoff + col]);
            float g = fmaf(accG[j][e], g_A[acoff + 128 + col],
                           g_C[acoff + 128 + col]);
            float y = o / (1.f + __expf(-g));
            float* hp = sm + S_HS + SWZ(col, row);
            if (RESID) y = (*hp + y) * RES_SCALE;
            *hp = y;
            afp[(col >> 5) * 2560 + row * 40 + (col & 31)] = __float2half(y);
        }
    }
    __syncthreads();
}

// ---------------- main kernel ----------------
__global__ void __launch_bounds__(NTH, 1) tabnet_kernel(
    const float* __restrict__ att_W, const float* __restrict__ out_W,
    const float* __restrict__ out_b, float* __restrict__ out)
{
    extern __shared__ float sm[];
    const int t = threadIdx.x;
    const int tile = blockIdx.x;
    const uint32_t smb = smem_u32(sm);

    for (int i = t; i < 5120; i += NTH) sm[S_MG + i] = 1.f;
    for (int i = t; i < 5120; i += NTH) sm[S_PR + i] = 1.f;
    for (int i = t; i < 4096; i += NTH) sm[S_DS + i] = 0.f;
    __syncthreads();

    // ---- init pass ----
    glu_mma<0, false>(10, 0,  OFF_SH0,        tile, sm, smb, t);
    glu_mma<1, true >(4,  10, OFF_SH1,        tile, sm, smb, t);
    glu_mma<1, true >(4,  14, OFF_INIT,       tile, sm, smb, t);
    glu_mma<1, true >(4,  18, OFF_INIT + 256, tile, sm, smb, t);

    for (int s = 0; s < 5; s++) {
        // ---- attention: logits = BN(a @ att_W[s]) * prior ----
        float* wsW = sm + S_W;
        float* lg  = sm + S_W + 5120;
        float* pr  = sm + S_PR;
        float* mg  = sm + S_MG;
        const float* hs = sm + S_HS;
        const float* aw = att_W + s * 5120;
        for (int i = t; i < 5120; i += NTH) wsW[i] = aw[i];
        __syncthreads();

        if (t < 256) {
            float acc[4][5];
            const int ra = (t >> 4) << 2;
            const int c5 = (t & 15) * 5;
#pragma unroll
            for (int rr = 0; rr < 4; rr++)
#pragma unroll
                for (int j = 0; j < 5; j++) acc[rr][j] = 0.f;
#pragma unroll 4
            for (int kk = 0; kk < 64; kk++) {
                int col = 64 + kk;
                float4 av = *(const float4*)(hs + col * 64 + (ra ^ (col & 0x1C)));
                float arr[4] = {av.x, av.y, av.z, av.w};
#pragma unroll
                for (int j = 0; j < 5; j++) {
                    float wv = wsW[kk * 80 + c5 + j];
#pragma unroll
                    for (int rr = 0; rr < 4; rr++)
                        acc[rr][j] = fmaf(arr[rr], wv, acc[rr][j]);
                }
            }
            __syncthreads();
#pragma unroll
            for (int j = 0; j < 5; j++) {
                int g = c5 + j;
                float A = g_A[OFF_ATT + s * 80 + g], C = g_C[OFF_ATT + s * 80 + g];
#pragma unroll
                for (int rr = 0; rr < 4; rr++) {
                    int r = ra + rr;
                    lg[r * 80 + g] = fmaf(acc[rr][j], A, C) * pr[r * 80 + g];
                }
            }
        } else {
            __syncthreads();
        }
        __syncthreads();

        // ---- sparsemax (Michelot) ----
        if (t < 64) {
            const float* z = lg + t * 80;
            float S = 0.f;
            for (int i = 0; i < 80; i++) S += z[i];
            int k = 80;
            float tau = (S - 1.f) / 80.f;
            for (int it = 0; it < 80; it++) {
                float S2 = 0.f; int k2 = 0;
                for (int i = 0; i < 80; i++) {
                    float zi = z[i];
                    if (zi > tau) { S2 += zi; k2++; }
                }
                if (k2 == k) break;
                k = k2;
                tau = (S2 - 1.f) / (float)k2;
            }
            for (int g = 0; g < 80; g++) {
                float m_ = z[g] - tau;
                m_ = m_ > 0.f ? m_ : 0.f;
                mg[SWZ(g, t)] = m_;
                pr[t * 80 + g] *= (GAMMA_C - m_);
            }
        }
        __syncthreads();

        // ---- masked ft pass ----
        glu_mma<0, false>(10, 0,      OFF_SH0,                  tile, sm, smb, t);
        glu_mma<1, true >(4,  10,     OFF_SH1,                  tile, sm, smb, t);
        glu_mma<1, true >(4,  22+8*s, OFF_STEP + (2*s) * 256,   tile, sm, smb, t);
        glu_mma<1, true >(4,  26+8*s, OFF_STEP + (2*s+1) * 256, tile, sm, smb, t);

        // ---- decision_sum += relu(d) ----
        for (int i = t; i < 4096; i += NTH) {
            float v = sm[S_HS + i];
            sm[S_DS + i] += v > 0.f ? v : 0.f;
        }
        __syncthreads();
    }

    // ---- final: out = ds @ out_W + out_b ----
    if (t < 64) {
        float sacc = 0.f;
#pragma unroll
        for (int j = 0; j < 64; j++)
            sacc = fmaf(sm[S_DS + SWZ(j, t)], out_W[j], sacc);
        out[tile * 64 + t] = sacc + out_b[0];
    }
}

extern "C" void kernel_launch(void* const* d_in, const int* in_sizes, int n_in,
                              void* d_out, int out_size)
{
    const float* x_num   = (const float*)d_in[0];
    const int*   x_cat   = (const int*)  d_in[1];
    const float* emb_W   = (const float*)d_in[2];
    const float* in_bn   = (const float*)d_in[3];
    const float* sh_W0   = (const float*)d_in[4];
    const float* sh_b0   = (const float*)d_in[5];
    const float* sh_bn0  = (const float*)d_in[6];
    const float* sh_W1   = (const float*)d_in[7];
    const float* sh_b1   = (const float*)d_in[8];
    const float* sh_bn1  = (const float*)d_in[9];
    const float* init_W  = (const float*)d_in[10];
    const float* init_b  = (const float*)d_in[11];
    const float* init_bn = (const float*)d_in[12];
    const float* step_W  = (const float*)d_in[13];
    const float* step_b  = (const float*)d_in[14];
    const float* step_bn = (const float*)d_in[15];
    const float* att_W   = (const float*)d_in[16];
    const float* att_b   = (const float*)d_in[17];
    const float* att_bn  = (const float*)d_in[18];
    const float* out_W   = (const float*)d_in[19];
    const float* out_b   = (const float*)d_in[20];
    float* out = (float*)d_out;

    cudaFuncSetAttribute(tabnet_kernel,
                         cudaFuncAttributeMaxDynamicSharedMemorySize, SMEM_BYTES);

    prep_kernel<<<(AC_TOTAL + 255) / 256, 256>>>(
        in_bn, sh_b0, sh_bn0, sh_b1, sh_bn1,
        init_b, init_bn, step_b, step_bn, att_b, att_bn);
    prep2_kernel<<<(62 * 8192 + 255) / 256, 256>>>(sh_W0, sh_W1, init_W, step_W);
    prep3_kernel<<<(int)(((size_t)NTILES * 20480) / 256), 256>>>(x_num, x_cat, emb_W);

    tabnet_kernel<<<NTILES, NTH, SMEM_BYTES>>>(att_W, out_W, out_b, out);
}